// round 6
// baseline (speedup 1.0000x reference)
#include <cuda_runtime.h>
#include <cuda_bf16.h>
#include <math.h>
#include <stdint.h>

#define NN 100000
#define NE 640000
#define IND 64
#define HH  128
#define NG  128

typedef unsigned long long u64;

// ---------------- scratch (static device globals) ----------------
__device__ float g_h [NN*HH];
__device__ float g_m [NN*HH];
__device__ float g_fb[NN*HH];
__device__ float g_gb[NN*HH];
__device__ float g_Wint[IND*HH];
__device__ float g_e  [NN];
__device__ int   g_bounds[NG+1];
__device__ float g_hl[NG*HH];
__device__ float g_cl[NG*HH];
__device__ float g_qs[NG*2*HH];
// padded bf16 hi/lo weight images: [128 j][264 k] (k = concat W|U + 8 pad)
#define WKP 264
__device__ __nv_bfloat16 g_Vf_hi[HH*WKP];
__device__ __nv_bfloat16 g_Vf_lo[HH*WKP];
__device__ __nv_bfloat16 g_Vh_hi[HH*WKP];
__device__ __nv_bfloat16 g_Vh_lo[HH*WKP];

__device__ __forceinline__ float sigf(float z)   { return __fdividef(1.f, 1.f + __expf(-z)); }
__device__ __forceinline__ float tanhfast(float z){ return 1.f - __fdividef(2.f, __expf(2.f*z) + 1.f); }

// ---- packed fp32x2 helpers (FFMA2) ----
__device__ __forceinline__ u64 dup2(float a){
    u64 r; asm("mov.b64 %0, {%1, %1};" : "=l"(r) : "f"(a)); return r;
}
__device__ __forceinline__ void ffma2(u64& d, u64 a, u64 b){
    asm("fma.rn.f32x2 %0, %1, %2, %0;" : "+l"(d) : "l"(a), "l"(b));
}
__device__ __forceinline__ float2 unpk(u64 v){
    float2 r; asm("mov.b64 {%0, %1}, %2;" : "=f"(r.x), "=f"(r.y) : "l"(v)); return r;
}

// ---- bf16 split helpers ----
__device__ __forceinline__ uint32_t pack_hi(float lo, float hi_e){
    uint32_t r; asm("cvt.rn.bf16x2.f32 %0, %1, %2;" : "=r"(r) : "f"(hi_e), "f"(lo)); return r;
}
// residual of packed pair
__device__ __forceinline__ float2 resid(float2 v, uint32_t hp){
    float r0 = __uint_as_float(hp << 16);
    float r1 = __uint_as_float(hp & 0xFFFF0000u);
    return make_float2(v.x - r0, v.y - r1);
}

// ---- mma.sync bf16 (sm_80+ baseline, works on plain sm_103 target) ----
__device__ __forceinline__ void mma_bf16(float* c, const uint32_t* a, uint32_t b0, uint32_t b1){
    asm volatile("mma.sync.aligned.m16n8k16.row.col.f32.bf16.bf16.f32 "
        "{%0,%1,%2,%3}, {%4,%5,%6,%7}, {%8,%9}, {%0,%1,%2,%3};"
        : "+f"(c[0]), "+f"(c[1]), "+f"(c[2]), "+f"(c[3])
        : "r"(a[0]), "r"(a[1]), "r"(a[2]), "r"(a[3]), "r"(b0), "r"(b1));
}

// ---------------- transpose (for W_in only) ----------------
__global__ void k_transpose(const float* __restrict__ src, float* __restrict__ dst, int R, int C){
    __shared__ float t[32][33];
    int c = blockIdx.x*32 + threadIdx.x;
    int r = blockIdx.y*32 + threadIdx.y;
    if (r < R && c < C) t[threadIdx.y][threadIdx.x] = src[r*C + c];
    __syncthreads();
    int rc = blockIdx.x*32 + threadIdx.y;
    int cc = blockIdx.y*32 + threadIdx.x;
    if (rc < C && cc < R) dst[rc*R + cc] = t[threadIdx.x][threadIdx.y];
}

// ---------------- weight prep: padded bf16 hi/lo images ----------------
__global__ void k_prepw(const float* __restrict__ Wf, const float* __restrict__ Uf,
                        const float* __restrict__ Wh, const float* __restrict__ Uh){
    int idx = blockIdx.x*blockDim.x + threadIdx.x;
    if (idx >= 2*HH*WKP) return;
    int pair = idx / (HH*WKP);
    int rem  = idx % (HH*WKP);
    int j = rem / WKP;
    int k = rem % WKP;
    float v = 0.f;
    if (k < 128)      v = (pair ? Wh : Wf)[j*128 + k];
    else if (k < 256) v = (pair ? Uh : Uf)[j*128 + (k-128)];
    __nv_bfloat16 hb = __float2bfloat16(v);
    float lo = v - __bfloat162float(hb);
    __nv_bfloat16 lb = __float2bfloat16(lo);
    (pair ? g_Vh_hi : g_Vf_hi)[rem] = hb;
    (pair ? g_Vh_lo : g_Vf_lo)[rem] = lb;
}

// ---------------- segment boundaries ----------------
__global__ void k_bounds(const int* __restrict__ batch){
    int i = blockIdx.x*blockDim.x + threadIdx.x;
    if (i >= NN) return;
    int b = batch[i];
    if (i == 0)      { for (int g = 0;    g <= b;  g++) g_bounds[g] = 0; }
    else             { int pb = batch[i-1];
                       for (int g = pb+1; g <= b;  g++) g_bounds[g] = i; }
    if (i == NN-1)   { for (int g = b+1;  g <= NG; g++) g_bounds[g] = NN; }
}

// ---------------- zero helpers ----------------
__global__ void k_zero4(float4* __restrict__ p, int n4){
    int i = blockIdx.x*blockDim.x + threadIdx.x;
    if (i < n4) p[i] = make_float4(0.f,0.f,0.f,0.f);
}
__global__ void k_zero_s2s(){
    int i = blockIdx.x*blockDim.x + threadIdx.x;
    if (i < NG*HH) { g_hl[i] = 0.f; g_cl[i] = 0.f; }
    if (i < NG*2*HH) g_qs[i] = 0.f;
}

// ---------------- input layer (FFMA2) ----------------
__global__ __launch_bounds__(256) void k_input(const float* __restrict__ x,
                                               const float* __restrict__ bin){
    extern __shared__ float sm[];
    float4* Ws4 = (float4*)sm;
    float4* Xs4 = (float4*)(sm + IND*HH);
    int tid = threadIdx.x;
    int jt = tid & 31, nt = tid >> 5;

    const float4* Wg = (const float4*)g_Wint;
#pragma unroll
    for (int i = 0; i < 8; i++) Ws4[tid + i*256] = Wg[tid + i*256];

    int base = blockIdx.x * 64;
    const float4* Xg = (const float4*)x;
#pragma unroll
    for (int i = 0; i < 4; i++){
        int q = tid + i*256;
        int rn = q >> 4, col = q & 15;
        int gn = base + rn;
        Xs4[q] = (gn < NN) ? Xg[gn*16 + col] : make_float4(0.f,0.f,0.f,0.f);
    }
    __syncthreads();

    u64 acc[8][2];
#pragma unroll
    for (int i = 0; i < 8; i++){ acc[i][0] = 0ull; acc[i][1] = 0ull; }

    for (int k = 0; k < IND; k += 4){
        float a[8][4];
#pragma unroll
        for (int i = 0; i < 8; i++){
            float4 t4 = Xs4[(nt*8+i)*16 + (k>>2)];
            a[i][0]=t4.x; a[i][1]=t4.y; a[i][2]=t4.z; a[i][3]=t4.w;
        }
#pragma unroll
        for (int kk = 0; kk < 4; kk++){
            ulonglong2 wv = ((const ulonglong2*)Ws4)[(k+kk)*32 + jt];
#pragma unroll
            for (int i = 0; i < 8; i++){
                u64 a2 = dup2(a[i][kk]);
                ffma2(acc[i][0], a2, wv.x);
                ffma2(acc[i][1], a2, wv.y);
            }
        }
    }
    float4 bb = ((const float4*)bin)[jt];
#pragma unroll
    for (int i = 0; i < 8; i++){
        int n = base + nt*8 + i;
        if (n < NN){
            float2 z01 = unpk(acc[i][0]);
            float2 z23 = unpk(acc[i][1]);
            float4 o;
            o.x = fmaxf(z01.x+bb.x, 0.f);
            o.y = fmaxf(z01.y+bb.y, 0.f);
            o.z = fmaxf(z23.x+bb.z, 0.f);
            o.w = fmaxf(z23.y+bb.w, 0.f);
            ((float4*)g_h)[n*32 + jt] = o;
        }
    }
}

// ---------------- edge scatter ----------------
__global__ void k_scatter(const int* __restrict__ src, const int* __restrict__ dst){
    int t = blockIdx.x*blockDim.x + threadIdx.x;
    int e = t >> 5;
    if (e >= NE) return;
    int lane = t & 31;
    int s = __ldg(&src[e]);
    int d = __ldg(&dst[e]);
    float4 v = ((const float4*)g_h)[s*32 + lane];
    float* p = g_m + d*HH + lane*4;
    asm volatile("red.global.add.v4.f32 [%0], {%1, %2, %3, %4};"
                 :: "l"(p), "f"(v.x), "f"(v.y), "f"(v.z), "f"(v.w) : "memory");
}

// ---------------- HMMA dual GEMM with MGU epilogue ----------------
// z[n][j] = sum_k [A|B][n][k] * [W|U][j][k] + bias[j]  (K=256 concat)
// 2-term bf16 split: Ahi*Whi + Alo*Whi + Ahi*Wlo, fp32 accum.
// MODE 0: f=sigmoid(z)->O1 ; g=f*h->O2 (h==B).  MODE 1: Hb = (1-Fb)*Hb + Fb*tanh(z).
// block: 64 nodes x 128 j, 8 warps (warp = 16 rows x 64 cols), persistent.
#define AKP 264
#define SMW (HH*WKP*2)                // bytes of one bf16 image = 67584; two images
#define SMEMG (2*HH*WKP*2 + 64*AKP*4) // Whi + Wlo + A(fp32) = 202752 B
template<int MODE>
__global__ __launch_bounds__(256, 1) void k_dualgemm_mma(
    const float* __restrict__ A, const float* __restrict__ B,
    const __nv_bfloat16* __restrict__ Vhi, const __nv_bfloat16* __restrict__ Vlo,
    const float* __restrict__ bias,
    float* __restrict__ O1, float* __restrict__ O2,
    const float* __restrict__ Fb, float* __restrict__ Hb)
{
    extern __shared__ char smem[];
    __nv_bfloat16* Whi = (__nv_bfloat16*)smem;                    // [128][264]
    __nv_bfloat16* Wlo = (__nv_bfloat16*)(smem + HH*WKP*2);       // [128][264]
    float*         As  = (float*)(smem + 2*HH*WKP*2);             // [64][264]
    int tid = threadIdx.x, wid = tid >> 5, lane = tid & 31;

    // copy weight images (pads included)
    {
        const uint4* gh = (const uint4*)Vhi;
        const uint4* gl = (const uint4*)Vlo;
        uint4* sh = (uint4*)Whi;
        uint4* sl = (uint4*)Wlo;
        const int n16 = HH*WKP*2/16;   // 4224
        for (int i = tid; i < n16; i += 256){ sh[i] = gh[i]; sl[i] = gl[i]; }
    }

    int wr = wid & 3;            // row group (16 rows)
    int wc = wid >> 2;           // col group (64 cols)
    int r0 = (lane >> 2);        // 0..7
    int kq = (lane & 3) * 2;     // 0,2,4,6

    // preload bias pairs for this thread's 8 n-tiles
    float2 bz[8];
#pragma unroll
    for (int nt = 0; nt < 8; nt++){
        int col = wc*64 + nt*8 + kq/2*2;   // == wc*64+nt*8+(lane%4)*2
        bz[nt] = *(const float2*)&bias[wc*64 + nt*8 + (lane&3)*2];
        (void)col;
    }

    const float4* Ag = (const float4*)A;
    const float4* Bg = (const float4*)B;

    int ntiles = (NN + 63) >> 6;
    for (int tile = blockIdx.x; tile < ntiles; tile += gridDim.x){
        int base = tile << 6;
        __syncthreads();   // previous tile's A reads complete
        // load A tile: 64 rows x 64 float4 (= [m row | h row]) into padded smem
#pragma unroll
        for (int i = 0; i < 16; i++){
            int q = tid + i*256;
            int row = q >> 6, c = q & 63;
            int gn = base + row;
            float4 v = make_float4(0.f,0.f,0.f,0.f);
            if (gn < NN) v = (c < 32) ? __ldg(Ag + (size_t)gn*32 + c)
                                      : __ldg(Bg + (size_t)gn*32 + (c-32));
            *(float4*)&As[row*AKP + c*4] = v;
        }
        __syncthreads();

        float c[8][4];
#pragma unroll
        for (int nt = 0; nt < 8; nt++){ c[nt][0]=0.f; c[nt][1]=0.f; c[nt][2]=0.f; c[nt][3]=0.f; }

#pragma unroll 4
        for (int ks = 0; ks < 16; ks++){
            int kb = ks * 16;
            // A fragments: rows wr*16 + r0 (+8), k = kb+kq (+8); fp32 -> hi/lo
            float2 v0 = *(const float2*)&As[(wr*16 + r0    )*AKP + kb + kq];
            float2 v1 = *(const float2*)&As[(wr*16 + r0 + 8)*AKP + kb + kq];
            float2 v2 = *(const float2*)&As[(wr*16 + r0    )*AKP + kb + 8 + kq];
            float2 v3 = *(const float2*)&As[(wr*16 + r0 + 8)*AKP + kb + 8 + kq];
            uint32_t ah[4], al[4];
            ah[0] = pack_hi(v0.x, v0.y);
            ah[1] = pack_hi(v1.x, v1.y);
            ah[2] = pack_hi(v2.x, v2.y);
            ah[3] = pack_hi(v3.x, v3.y);
            float2 l0 = resid(v0, ah[0]), l1 = resid(v1, ah[1]);
            float2 l2 = resid(v2, ah[2]), l3 = resid(v3, ah[3]);
            al[0] = pack_hi(l0.x, l0.y);
            al[1] = pack_hi(l1.x, l1.y);
            al[2] = pack_hi(l2.x, l2.y);
            al[3] = pack_hi(l3.x, l3.y);

#pragma unroll
            for (int nt = 0; nt < 8; nt++){
                int col = wc*64 + nt*8 + (lane >> 2);
                const __nv_bfloat16* wrow = Whi + col*WKP + kb;
                const __nv_bfloat16* lrow = Wlo + col*WKP + kb;
                uint32_t bh0 = *(const uint32_t*)(wrow + kq);
                uint32_t bh1 = *(const uint32_t*)(wrow + 8 + kq);
                uint32_t bl0 = *(const uint32_t*)(lrow + kq);
                uint32_t bl1 = *(const uint32_t*)(lrow + 8 + kq);
                mma_bf16(c[nt], ah, bh0, bh1);
                mma_bf16(c[nt], al, bh0, bh1);
                mma_bf16(c[nt], ah, bl0, bl1);
            }
        }

        // epilogue: thread owns rows n0=base+wr*16+r0, n1=n0+8; cols wc*64+nt*8+(lane%4)*2
        int n0 = base + wr*16 + r0;
        int n1 = n0 + 8;
        bool ok0 = (n0 < NN), ok1 = (n1 < NN);
#pragma unroll
        for (int nt = 0; nt < 8; nt++){
            int col = wc*64 + nt*8 + (lane & 3)*2;
            if (MODE == 0){
                float f00 = sigf(c[nt][0] + bz[nt].x);
                float f01 = sigf(c[nt][1] + bz[nt].y);
                float f10 = sigf(c[nt][2] + bz[nt].x);
                float f11 = sigf(c[nt][3] + bz[nt].y);
                if (ok0){
                    float2 hv = *(const float2*)&B[(size_t)n0*HH + col];
                    *(float2*)&O1[(size_t)n0*HH + col] = make_float2(f00, f01);
                    *(float2*)&O2[(size_t)n0*HH + col] = make_float2(f00*hv.x, f01*hv.y);
                }
                if (ok1){
                    float2 hv = *(const float2*)&B[(size_t)n1*HH + col];
                    *(float2*)&O1[(size_t)n1*HH + col] = make_float2(f10, f11);
                    *(float2*)&O2[(size_t)n1*HH + col] = make_float2(f10*hv.x, f11*hv.y);
                }
            } else {
                float t00 = tanhfast(c[nt][0] + bz[nt].x);
                float t01 = tanhfast(c[nt][1] + bz[nt].y);
                float t10 = tanhfast(c[nt][2] + bz[nt].x);
                float t11 = tanhfast(c[nt][3] + bz[nt].y);
                if (ok0){
                    float2 fv = *(const float2*)&Fb[(size_t)n0*HH + col];
                    float2 hv = *(const float2*)&Hb[(size_t)n0*HH + col];
                    *(float2*)&Hb[(size_t)n0*HH + col] =
                        make_float2((1.f-fv.x)*hv.x + fv.x*t00, (1.f-fv.y)*hv.y + fv.y*t01);
                }
                if (ok1){
                    float2 fv = *(const float2*)&Fb[(size_t)n1*HH + col];
                    float2 hv = *(const float2*)&Hb[(size_t)n1*HH + col];
                    *(float2*)&Hb[(size_t)n1*HH + col] =
                        make_float2((1.f-fv.x)*hv.x + fv.x*t10, (1.f-fv.y)*hv.y + fv.y*t11);
                }
            }
        }
    }
}

// ---------------- Set2Set LSTM ----------------
__global__ __launch_bounds__(512) void k_lstm(const float* __restrict__ wih,
                                              const float* __restrict__ whh,
                                              const float* __restrict__ bih,
                                              const float* __restrict__ bhh){
    __shared__ float qs[2*HH];
    __shared__ float hs[HH];
    __shared__ float gt[4*HH];
    int g = blockIdx.x, t = threadIdx.x;
    if (t < 2*HH) qs[t] = g_qs[g*2*HH + t];
    if (t < HH)   hs[t] = g_hl[g*HH + t];
    __syncthreads();

    float acc = bih[t] + bhh[t];
    const float4* wr  = (const float4*)(wih + t*2*HH);
    const float4* qs4 = (const float4*)qs;
#pragma unroll 8
    for (int k = 0; k < 64; k++){
        float4 w = wr[k], q = qs4[k];
        acc += w.x*q.x + w.y*q.y + w.z*q.z + w.w*q.w;
    }
    const float4* hr  = (const float4*)(whh + t*HH);
    const float4* hs4 = (const float4*)hs;
#pragma unroll 8
    for (int k = 0; k < 32; k++){
        float4 w = hr[k], q = hs4[k];
        acc += w.x*q.x + w.y*q.y + w.z*q.z + w.w*q.w;
    }
    gt[t] = acc;
    __syncthreads();

    if (t < HH){
        float ig = gt[t], fg = gt[HH+t], gg = gt[2*HH+t], og = gt[3*HH+t];
        float c = sigf(fg)*g_cl[g*HH+t] + sigf(ig)*tanhfast(gg);
        g_cl[g*HH+t] = c;
        g_hl[g*HH+t] = sigf(og)*tanhfast(c);
    }
}

// ---------------- Set2Set attention ----------------
__global__ __launch_bounds__(256) void k_attn(){
    __shared__ float q[HH];
    __shared__ float red[8];
    __shared__ float rp[8][HH];
    int g = blockIdx.x, t = threadIdx.x, wid = t >> 5, lane = t & 31;
    int s = g_bounds[g], e = g_bounds[g+1];

    if (t < HH){ float qv = g_hl[g*HH + t]; q[t] = qv; g_qs[g*2*HH + t] = qv; }
    __syncthreads();

    const float4* h4 = (const float4*)g_h;
    float4 q4 = ((float4*)q)[lane];

    float lmax = -3.4e38f;
    for (int n = s + wid; n < e; n += 8){
        float4 x4 = h4[n*32 + lane];
        float p = x4.x*q4.x + x4.y*q4.y + x4.z*q4.z + x4.w*q4.w;
#pragma unroll
        for (int o = 16; o; o >>= 1) p += __shfl_xor_sync(0xffffffffu, p, o);
        if (lane == 0) g_e[n] = p;
        lmax = fmaxf(lmax, p);
    }
    if (lane == 0) red[wid] = lmax;
    __syncthreads();
    float emax = -3.4e38f;
#pragma unroll
    for (int w = 0; w < 8; w++) emax = fmaxf(emax, red[w]);
    __syncthreads();

    float lsum = 0.f;
    for (int n = s + t; n < e; n += 256){
        float w = __expf(g_e[n] - emax);
        g_e[n] = w;
        lsum += w;
    }
#pragma unroll
    for (int o = 16; o; o >>= 1) lsum += __shfl_xor_sync(0xffffffffu, lsum, o);
    if (lane == 0) red[wid] = lsum;
    __syncthreads();
    float denom = 0.f;
#pragma unroll
    for (int w = 0; w < 8; w++) denom += red[w];

    float4 racc = make_float4(0.f,0.f,0.f,0.f);
    for (int n = s + wid; n < e; n += 8){
        float coef = g_e[n];
        float4 x4 = h4[n*32 + lane];
        racc.x += coef*x4.x; racc.y += coef*x4.y;
        racc.z += coef*x4.z; racc.w += coef*x4.w;
    }
    ((float4*)rp[wid])[lane] = racc;
    __syncthreads();
    if (t < HH){
        float r = 0.f;
#pragma unroll
        for (int w = 0; w < 8; w++) r += rp[w][t];
        r = (e > s) ? (r / denom) : 0.f;
        g_qs[g*2*HH + HH + t] = r;
    }
}

// ---------------- prediction ----------------
__global__ __launch_bounds__(128) void k_pred(const float* __restrict__ wp,
                                              const float* __restrict__ bp,
                                              float* __restrict__ out){
    __shared__ float red[4];
    int g = blockIdx.x, t = threadIdx.x;
    float p = g_qs[g*256 + t]*wp[t] + g_qs[g*256 + 128 + t]*wp[128 + t];
#pragma unroll
    for (int o = 16; o; o >>= 1) p += __shfl_xor_sync(0xffffffffu, p, o);
    if ((t & 31) == 0) red[t >> 5] = p;
    __syncthreads();
    if (t == 0) out[g] = red[0] + red[1] + red[2] + red[3] + bp[0];
}

// ---------------- launcher ----------------
extern "C" void kernel_launch(void* const* d_in, const int* in_sizes, int n_in,
                              void* d_out, int out_size){
    const float* x    = (const float*)d_in[0];
    const int*   ei   = (const int*)  d_in[1];
    const int*   batch= (const int*)  d_in[2];
    const float* Win  = (const float*)d_in[3];
    const float* bin  = (const float*)d_in[4];
    const float* Wf   = (const float*)d_in[5];
    const float* Uf   = (const float*)d_in[6];
    const float* bf   = (const float*)d_in[7];
    const float* Wh   = (const float*)d_in[8];
    const float* Uh   = (const float*)d_in[9];
    const float* bh   = (const float*)d_in[10];
    const float* wih  = (const float*)d_in[11];
    const float* whh  = (const float*)d_in[12];
    const float* bih  = (const float*)d_in[13];
    const float* bhh  = (const float*)d_in[14];
    const float* wp   = (const float*)d_in[15];
    const float* bp   = (const float*)d_in[16];
    float* out = (float*)d_out;

    float *p_m, *p_h, *p_fb, *p_gb, *p_Wint;
    __nv_bfloat16 *p_Vfh, *p_Vfl, *p_Vhh, *p_Vhl;
    cudaGetSymbolAddress((void**)&p_m,    g_m);
    cudaGetSymbolAddress((void**)&p_h,    g_h);
    cudaGetSymbolAddress((void**)&p_fb,   g_fb);
    cudaGetSymbolAddress((void**)&p_gb,   g_gb);
    cudaGetSymbolAddress((void**)&p_Wint, g_Wint);
    cudaGetSymbolAddress((void**)&p_Vfh,  g_Vf_hi);
    cudaGetSymbolAddress((void**)&p_Vfl,  g_Vf_lo);
    cudaGetSymbolAddress((void**)&p_Vhh,  g_Vh_hi);
    cudaGetSymbolAddress((void**)&p_Vhl,  g_Vh_lo);

    cudaFuncSetAttribute(k_dualgemm_mma<0>, cudaFuncAttributeMaxDynamicSharedMemorySize, SMEMG);
    cudaFuncSetAttribute(k_dualgemm_mma<1>, cudaFuncAttributeMaxDynamicSharedMemorySize, SMEMG);
    cudaFuncSetAttribute(k_input,           cudaFuncAttributeMaxDynamicSharedMemorySize, 49152);

    dim3 tb(32, 32);
    k_transpose<<<dim3(2,4), tb>>>(Win, p_Wint, 128, 64);
    k_prepw<<<(2*HH*WKP + 255)/256, 256>>>(Wf, Uf, Wh, Uh);
    k_bounds<<<(NN+255)/256, 256>>>(batch);
    k_input<<<(NN+63)/64, 256, 49152>>>(x, bin);

    for (int step = 0; step < 3; step++){
        k_zero4<<<(NN*HH/4 + 255)/256, 256>>>((float4*)p_m, NN*HH/4);
        k_scatter<<<(NE*32)/256, 256>>>(ei, ei + NE);
        k_dualgemm_mma<0><<<152, 256, SMEMG>>>(p_m, p_h,  p_Vfh, p_Vfl, bf, p_fb, p_gb, nullptr, nullptr);
        k_dualgemm_mma<1><<<152, 256, SMEMG>>>(p_m, p_gb, p_Vhh, p_Vhl, bh, nullptr, nullptr, p_fb, p_h);
    }

    k_zero_s2s<<<(NG*2*HH + 255)/256, 256>>>();
    for (int step = 0; step < 3; step++){
        k_lstm<<<NG, 512>>>(wih, whh, bih, bhh);
        k_attn<<<NG, 256>>>();
    }
    k_pred<<<NG, 128>>>(wp, bp, out);
}

// round 7
// speedup vs baseline: 1.0666x; 1.0666x over previous
#include <cuda_runtime.h>
#include <cuda_bf16.h>
#include <math.h>
#include <stdint.h>

#define NN 100000
#define NE 640000
#define IND 64
#define HH  128
#define NG  128

typedef unsigned long long u64;

// ---------------- scratch (static device globals) ----------------
__device__ float g_h [NN*HH];
__device__ float g_m [NN*HH];
__device__ float g_fb[NN*HH];
__device__ float g_gb[NN*HH];
__device__ float g_Wint[IND*HH];
__device__ float g_Wft[HH*HH];
__device__ float g_Uft[HH*HH];
__device__ float g_Wht[HH*HH];
__device__ float g_Uht[HH*HH];
__device__ float g_e  [NN];
__device__ int   g_bounds[NG+1];
__device__ float g_hl[NG*HH];
__device__ float g_cl[NG*HH];
__device__ float g_qs[NG*2*HH];
// CSR scratch
__device__ int g_deg[NN];        // histogram, then reused as fill cursor
__device__ int g_off[NN+1];
__device__ int g_csr[NE];
__device__ int g_bsum[128];

__device__ __forceinline__ float sigf(float z)   { return __fdividef(1.f, 1.f + __expf(-z)); }
__device__ __forceinline__ float tanhfast(float z){ return 1.f - __fdividef(2.f, __expf(2.f*z) + 1.f); }

// ---- packed fp32x2 helpers (FFMA2) ----
__device__ __forceinline__ u64 dup2(float a){
    u64 r; asm("mov.b64 %0, {%1, %1};" : "=l"(r) : "f"(a)); return r;
}
__device__ __forceinline__ void ffma2(u64& d, u64 a, u64 b){
    asm("fma.rn.f32x2 %0, %1, %2, %0;" : "+l"(d) : "l"(a), "l"(b));
}
__device__ __forceinline__ float2 unpk(u64 v){
    float2 r; asm("mov.b64 {%0, %1}, %2;" : "=f"(r.x), "=f"(r.y) : "l"(v)); return r;
}

// ---------------- transpose: src[R][C] -> dst[C][R] ----------------
__global__ void k_transpose(const float* __restrict__ src, float* __restrict__ dst, int R, int C){
    __shared__ float t[32][33];
    int c = blockIdx.x*32 + threadIdx.x;
    int r = blockIdx.y*32 + threadIdx.y;
    if (r < R && c < C) t[threadIdx.y][threadIdx.x] = src[r*C + c];
    __syncthreads();
    int rc = blockIdx.x*32 + threadIdx.y;
    int cc = blockIdx.y*32 + threadIdx.x;
    if (rc < C && cc < R) dst[rc*R + cc] = t[threadIdx.x][threadIdx.y];
}

// ---------------- segment boundaries from sorted batch ----------------
__global__ void k_bounds(const int* __restrict__ batch){
    int i = blockIdx.x*blockDim.x + threadIdx.x;
    if (i >= NN) return;
    int b = batch[i];
    if (i == 0)      { for (int g = 0;    g <= b;  g++) g_bounds[g] = 0; }
    else             { int pb = batch[i-1];
                       for (int g = pb+1; g <= b;  g++) g_bounds[g] = i; }
    if (i == NN-1)   { for (int g = b+1;  g <= NG; g++) g_bounds[g] = NN; }
}

__global__ void k_zero_s2s(){
    int i = blockIdx.x*blockDim.x + threadIdx.x;
    if (i < NG*HH) { g_hl[i] = 0.f; g_cl[i] = 0.f; }
    if (i < NG*2*HH) g_qs[i] = 0.f;
}

// ---------------- CSR build ----------------
__global__ void k_zero_deg(){
    int i = blockIdx.x*blockDim.x + threadIdx.x;
    if (i < NN) g_deg[i] = 0;
}
__global__ void k_hist(const int* __restrict__ dst){
    int e = blockIdx.x*blockDim.x + threadIdx.x;
    if (e < NE) atomicAdd(&g_deg[dst[e]], 1);
}
// per-1024-block exclusive scan (Hillis-Steele inclusive, then subtract)
__global__ __launch_bounds__(1024) void k_scan1(){
    __shared__ int sd[1024];
    int t = threadIdx.x, i = blockIdx.x*1024 + t;
    int v = (i < NN) ? g_deg[i] : 0;
    sd[t] = v; __syncthreads();
#pragma unroll
    for (int o = 1; o < 1024; o <<= 1){
        int x = (t >= o) ? sd[t-o] : 0;
        __syncthreads();
        sd[t] += x;
        __syncthreads();
    }
    if (i < NN) g_off[i] = sd[t] - v;
    if (t == 1023) g_bsum[blockIdx.x] = sd[1023];
}
__global__ __launch_bounds__(128) void k_scan2(int nb){
    __shared__ int sd[128];
    int t = threadIdx.x;
    int v = (t < nb) ? g_bsum[t] : 0;
    sd[t] = v; __syncthreads();
#pragma unroll
    for (int o = 1; o < 128; o <<= 1){
        int x = (t >= o) ? sd[t-o] : 0;
        __syncthreads();
        sd[t] += x;
        __syncthreads();
    }
    if (t < nb) g_bsum[t] = sd[t] - v;   // exclusive
}
__global__ void k_scan3(){
    int i = blockIdx.x*blockDim.x + threadIdx.x;
    if (i < NN) g_off[i] += g_bsum[i >> 10];
    if (i == 0) g_off[NN] = NE;
}
__global__ void k_curinit(){
    int i = blockIdx.x*blockDim.x + threadIdx.x;
    if (i < NN) g_deg[i] = g_off[i];
}
__global__ void k_fill(const int* __restrict__ src, const int* __restrict__ dst){
    int e = blockIdx.x*blockDim.x + threadIdx.x;
    if (e >= NE) return;
    int pos = atomicAdd(&g_deg[dst[e]], 1);
    g_csr[pos] = src[e];
}

// ---------------- aggregation: m[n] = sum_{e in csr[n]} h[src_e] ----------------
__global__ __launch_bounds__(256) void k_agg(){
    int w = (blockIdx.x*blockDim.x + threadIdx.x) >> 5;
    if (w >= NN) return;
    int lane = threadIdx.x & 31;
    int s = __ldg(&g_off[w]), e = __ldg(&g_off[w+1]);
    const float4* h4 = (const float4*)g_h;
    float4 acc = make_float4(0.f,0.f,0.f,0.f);
    int p = s;
    for (; p + 1 < e; p += 2){
        int s0 = __ldg(&g_csr[p]);
        int s1 = __ldg(&g_csr[p+1]);
        float4 v0 = __ldg(h4 + (size_t)s0*32 + lane);
        float4 v1 = __ldg(h4 + (size_t)s1*32 + lane);
        acc.x += v0.x; acc.y += v0.y; acc.z += v0.z; acc.w += v0.w;
        acc.x += v1.x; acc.y += v1.y; acc.z += v1.z; acc.w += v1.w;
    }
    if (p < e){
        int s0 = __ldg(&g_csr[p]);
        float4 v0 = __ldg(h4 + (size_t)s0*32 + lane);
        acc.x += v0.x; acc.y += v0.y; acc.z += v0.z; acc.w += v0.w;
    }
    ((float4*)g_m)[(size_t)w*32 + lane] = acc;
}

// ---------------- input layer (FFMA2) ----------------
__global__ __launch_bounds__(256) void k_input(const float* __restrict__ x,
                                               const float* __restrict__ bin){
    extern __shared__ float sm[];
    float4* Ws4 = (float4*)sm;
    float4* Xs4 = (float4*)(sm + IND*HH);
    int tid = threadIdx.x;
    int jt = tid & 31, nt = tid >> 5;

    const float4* Wg = (const float4*)g_Wint;
#pragma unroll
    for (int i = 0; i < 8; i++) Ws4[tid + i*256] = Wg[tid + i*256];

    int base = blockIdx.x * 64;
    const float4* Xg = (const float4*)x;
#pragma unroll
    for (int i = 0; i < 4; i++){
        int q = tid + i*256;
        int rn = q >> 4, col = q & 15;
        int gn = base + rn;
        Xs4[q] = (gn < NN) ? Xg[gn*16 + col] : make_float4(0.f,0.f,0.f,0.f);
    }
    __syncthreads();

    u64 acc[8][2];
#pragma unroll
    for (int i = 0; i < 8; i++){ acc[i][0] = 0ull; acc[i][1] = 0ull; }

    for (int k = 0; k < IND; k += 4){
        float a[8][4];
#pragma unroll
        for (int i = 0; i < 8; i++){
            float4 t4 = Xs4[(nt*8+i)*16 + (k>>2)];
            a[i][0]=t4.x; a[i][1]=t4.y; a[i][2]=t4.z; a[i][3]=t4.w;
        }
#pragma unroll
        for (int kk = 0; kk < 4; kk++){
            ulonglong2 wv = ((const ulonglong2*)Ws4)[(k+kk)*32 + jt];
#pragma unroll
            for (int i = 0; i < 8; i++){
                u64 a2 = dup2(a[i][kk]);
                ffma2(acc[i][0], a2, wv.x);
                ffma2(acc[i][1], a2, wv.y);
            }
        }
    }
    float4 bb = ((const float4*)bin)[jt];
#pragma unroll
    for (int i = 0; i < 8; i++){
        int n = base + nt*8 + i;
        if (n < NN){
            float2 z01 = unpk(acc[i][0]);
            float2 z23 = unpk(acc[i][1]);
            float4 o;
            o.x = fmaxf(z01.x+bb.x, 0.f);
            o.y = fmaxf(z01.y+bb.y, 0.f);
            o.z = fmaxf(z23.x+bb.z, 0.f);
            o.w = fmaxf(z23.y+bb.w, 0.f);
            ((float4*)g_h)[n*32 + jt] = o;
        }
    }
}

// ---------------- dual GEMM (FFMA2, 512 threads) with MGU epilogue ----------------
// z = A@Wt + B@Ut + bias (K=2x128). MODE 0: f=sigmoid(z)->O1, g=f*h->O2.
// MODE 1: Hb = (1-Fb)*Hb + Fb*tanh(z) in place.
// block: 64 nodes x 128 j; 512 threads, thread = 4n x 4j; persistent grid.
#define SMG ((HH*HH*2 + 64*HH*2) * 4)
template<int MODE>
__global__ __launch_bounds__(512, 1) void k_dualgemm(
    const float* __restrict__ A, const float* __restrict__ B,
    const float* __restrict__ Wt, const float* __restrict__ Ut,
    const float* __restrict__ bias,
    float* __restrict__ O1, float* __restrict__ O2,
    const float* __restrict__ Fb, float* __restrict__ Hb)
{
    extern __shared__ float sm[];
    float4* Ws4 = (float4*)sm;                       // 4096 f4 (k-major)
    float4* Us4 = (float4*)(sm + HH*HH);             // 4096 f4
    float4* As4 = (float4*)(sm + 2*HH*HH);           // 2048 f4
    float4* Bs4 = (float4*)(sm + 2*HH*HH + 64*HH);   // 2048 f4
    int tid = threadIdx.x;
    int jt = tid & 31, rt = tid >> 5;                // rt: 0..15, rows rt*4..rt*4+3

    const float4* Wg = (const float4*)Wt;
    const float4* Ug = (const float4*)Ut;
#pragma unroll
    for (int i = 0; i < 8; i++){
        Ws4[tid + i*512] = Wg[tid + i*512];
        Us4[tid + i*512] = Ug[tid + i*512];
    }
    float4 bb = ((const float4*)bias)[jt];
    const float4* Ag = (const float4*)A;
    const float4* Bg = (const float4*)B;

    int ntiles = (NN + 63) >> 6;
    for (int tile = blockIdx.x; tile < ntiles; tile += gridDim.x){
        __syncthreads();
        int base = tile << 6;
#pragma unroll
        for (int i = 0; i < 4; i++){
            int q = tid + i*512;
            int rn = q >> 5, col = q & 31;
            int gn = base + rn;
            if (gn < NN){ As4[q] = Ag[(size_t)gn*32 + col]; Bs4[q] = Bg[(size_t)gn*32 + col]; }
            else        { float4 z = make_float4(0.f,0.f,0.f,0.f); As4[q] = z; Bs4[q] = z; }
        }
        __syncthreads();

        u64 acc[4][2];
#pragma unroll
        for (int i = 0; i < 4; i++){ acc[i][0] = 0ull; acc[i][1] = 0ull; }

        for (int k = 0; k < HH; k += 4){
            float a[4][4], b[4][4];
#pragma unroll
            for (int i = 0; i < 4; i++){
                float4 ta = As4[(rt*4+i)*32 + (k>>2)];
                float4 tb = Bs4[(rt*4+i)*32 + (k>>2)];
                a[i][0]=ta.x; a[i][1]=ta.y; a[i][2]=ta.z; a[i][3]=ta.w;
                b[i][0]=tb.x; b[i][1]=tb.y; b[i][2]=tb.z; b[i][3]=tb.w;
            }
#pragma unroll
            for (int kk = 0; kk < 4; kk++){
                ulonglong2 wv = ((const ulonglong2*)Ws4)[(k+kk)*32 + jt];
                ulonglong2 uv = ((const ulonglong2*)Us4)[(k+kk)*32 + jt];
#pragma unroll
                for (int i = 0; i < 4; i++){
                    u64 a2 = dup2(a[i][kk]);
                    u64 b2 = dup2(b[i][kk]);
                    ffma2(acc[i][0], a2, wv.x);
                    ffma2(acc[i][1], a2, wv.y);
                    ffma2(acc[i][0], b2, uv.x);
                    ffma2(acc[i][1], b2, uv.y);
                }
            }
        }

#pragma unroll
        for (int i = 0; i < 4; i++){
            int n = base + rt*4 + i;
            if (n < NN){
                float2 z01 = unpk(acc[i][0]);
                float2 z23 = unpk(acc[i][1]);
                float z0 = z01.x+bb.x, z1 = z01.y+bb.y;
                float z2 = z23.x+bb.z, z3 = z23.y+bb.w;
                if (MODE == 0){
                    float f0 = sigf(z0), f1 = sigf(z1), f2 = sigf(z2), f3 = sigf(z3);
                    float4 hv = Bs4[(rt*4+i)*32 + jt];
                    ((float4*)O1)[(size_t)n*32 + jt] = make_float4(f0, f1, f2, f3);
                    ((float4*)O2)[(size_t)n*32 + jt] = make_float4(f0*hv.x, f1*hv.y, f2*hv.z, f3*hv.w);
                } else {
                    float4 fv = ((const float4*)Fb)[(size_t)n*32 + jt];
                    float4 hv = ((const float4*)Hb)[(size_t)n*32 + jt];
                    float4 o;
                    o.x = (1.f-fv.x)*hv.x + fv.x*tanhfast(z0);
                    o.y = (1.f-fv.y)*hv.y + fv.y*tanhfast(z1);
                    o.z = (1.f-fv.z)*hv.z + fv.z*tanhfast(z2);
                    o.w = (1.f-fv.w)*hv.w + fv.w*tanhfast(z3);
                    ((float4*)Hb)[(size_t)n*32 + jt] = o;
                }
            }
        }
    }
}

// ---------------- Set2Set LSTM ----------------
__global__ __launch_bounds__(512) void k_lstm(const float* __restrict__ wih,
                                              const float* __restrict__ whh,
                                              const float* __restrict__ bih,
                                              const float* __restrict__ bhh){
    __shared__ float qs[2*HH];
    __shared__ float hs[HH];
    __shared__ float gt[4*HH];
    int g = blockIdx.x, t = threadIdx.x;
    if (t < 2*HH) qs[t] = g_qs[g*2*HH + t];
    if (t < HH)   hs[t] = g_hl[g*HH + t];
    __syncthreads();

    float acc = bih[t] + bhh[t];
    const float4* wr  = (const float4*)(wih + t*2*HH);
    const float4* qs4 = (const float4*)qs;
#pragma unroll 8
    for (int k = 0; k < 64; k++){
        float4 w = wr[k], q = qs4[k];
        acc += w.x*q.x + w.y*q.y + w.z*q.z + w.w*q.w;
    }
    const float4* hr  = (const float4*)(whh + t*HH);
    const float4* hs4 = (const float4*)hs;
#pragma unroll 8
    for (int k = 0; k < 32; k++){
        float4 w = hr[k], q = hs4[k];
        acc += w.x*q.x + w.y*q.y + w.z*q.z + w.w*q.w;
    }
    gt[t] = acc;
    __syncthreads();

    if (t < HH){
        float ig = gt[t], fg = gt[HH+t], gg = gt[2*HH+t], og = gt[3*HH+t];
        float c = sigf(fg)*g_cl[g*HH+t] + sigf(ig)*tanhfast(gg);
        g_cl[g*HH+t] = c;
        g_hl[g*HH+t] = sigf(og)*tanhfast(c);
    }
}

// ---------------- Set2Set attention ----------------
__global__ __launch_bounds__(256) void k_attn(){
    __shared__ float q[HH];
    __shared__ float red[8];
    __shared__ float rp[8][HH];
    int g = blockIdx.x, t = threadIdx.x, wid = t >> 5, lane = t & 31;
    int s = g_bounds[g], e = g_bounds[g+1];

    if (t < HH){ float qv = g_hl[g*HH + t]; q[t] = qv; g_qs[g*2*HH + t] = qv; }
    __syncthreads();

    const float4* h4 = (const float4*)g_h;
    float4 q4 = ((float4*)q)[lane];

    float lmax = -3.4e38f;
    for (int n = s + wid; n < e; n += 8){
        float4 x4 = h4[n*32 + lane];
        float p = x4.x*q4.x + x4.y*q4.y + x4.z*q4.z + x4.w*q4.w;
#pragma unroll
        for (int o = 16; o; o >>= 1) p += __shfl_xor_sync(0xffffffffu, p, o);
        if (lane == 0) g_e[n] = p;
        lmax = fmaxf(lmax, p);
    }
    if (lane == 0) red[wid] = lmax;
    __syncthreads();
    float emax = -3.4e38f;
#pragma unroll
    for (int w = 0; w < 8; w++) emax = fmaxf(emax, red[w]);
    __syncthreads();

    float lsum = 0.f;
    for (int n = s + t; n < e; n += 256){
        float w = __expf(g_e[n] - emax);
        g_e[n] = w;
        lsum += w;
    }
#pragma unroll
    for (int o = 16; o; o >>= 1) lsum += __shfl_xor_sync(0xffffffffu, lsum, o);
    if (lane == 0) red[wid] = lsum;
    __syncthreads();
    float denom = 0.f;
#pragma unroll
    for (int w = 0; w < 8; w++) denom += red[w];

    float4 racc = make_float4(0.f,0.f,0.f,0.f);
    for (int n = s + wid; n < e; n += 8){
        float coef = g_e[n];
        float4 x4 = h4[n*32 + lane];
        racc.x += coef*x4.x; racc.y += coef*x4.y;
        racc.z += coef*x4.z; racc.w += coef*x4.w;
    }
    ((float4*)rp[wid])[lane] = racc;
    __syncthreads();
    if (t < HH){
        float r = 0.f;
#pragma unroll
        for (int w = 0; w < 8; w++) r += rp[w][t];
        r = (e > s) ? (r / denom) : 0.f;
        g_qs[g*2*HH + HH + t] = r;
    }
}

// ---------------- prediction ----------------
__global__ __launch_bounds__(128) void k_pred(const float* __restrict__ wp,
                                              const float* __restrict__ bp,
                                              float* __restrict__ out){
    __shared__ float red[4];
    int g = blockIdx.x, t = threadIdx.x;
    float p = g_qs[g*256 + t]*wp[t] + g_qs[g*256 + 128 + t]*wp[128 + t];
#pragma unroll
    for (int o = 16; o; o >>= 1) p += __shfl_xor_sync(0xffffffffu, p, o);
    if ((t & 31) == 0) red[t >> 5] = p;
    __syncthreads();
    if (t == 0) out[g] = red[0] + red[1] + red[2] + red[3] + bp[0];
}

// ---------------- launcher ----------------
extern "C" void kernel_launch(void* const* d_in, const int* in_sizes, int n_in,
                              void* d_out, int out_size){
    const float* x    = (const float*)d_in[0];
    const int*   ei   = (const int*)  d_in[1];
    const int*   batch= (const int*)  d_in[2];
    const float* Win  = (const float*)d_in[3];
    const float* bin  = (const float*)d_in[4];
    const float* Wf   = (const float*)d_in[5];
    const float* Uf   = (const float*)d_in[6];
    const float* bf   = (const float*)d_in[7];
    const float* Wh   = (const float*)d_in[8];
    const float* Uh   = (const float*)d_in[9];
    const float* bh   = (const float*)d_in[10];
    const float* wih  = (const float*)d_in[11];
    const float* whh  = (const float*)d_in[12];
    const float* bih  = (const float*)d_in[13];
    const float* bhh  = (const float*)d_in[14];
    const float* wp   = (const float*)d_in[15];
    const float* bp   = (const float*)d_in[16];
    float* out = (float*)d_out;

    float *p_m, *p_h, *p_fb, *p_gb, *p_Wint, *p_Wft, *p_Uft, *p_Wht, *p_Uht;
    cudaGetSymbolAddress((void**)&p_m,    g_m);
    cudaGetSymbolAddress((void**)&p_h,    g_h);
    cudaGetSymbolAddress((void**)&p_fb,   g_fb);
    cudaGetSymbolAddress((void**)&p_gb,   g_gb);
    cudaGetSymbolAddress((void**)&p_Wint, g_Wint);
    cudaGetSymbolAddress((void**)&p_Wft,  g_Wft);
    cudaGetSymbolAddress((void**)&p_Uft,  g_Uft);
    cudaGetSymbolAddress((void**)&p_Wht,  g_Wht);
    cudaGetSymbolAddress((void**)&p_Uht,  g_Uht);

    cudaFuncSetAttribute(k_dualgemm<0>, cudaFuncAttributeMaxDynamicSharedMemorySize, SMG);
    cudaFuncSetAttribute(k_dualgemm<1>, cudaFuncAttributeMaxDynamicSharedMemorySize, SMG);
    cudaFuncSetAttribute(k_input,       cudaFuncAttributeMaxDynamicSharedMemorySize, 49152);

    const int* esrc = ei;
    const int* edst = ei + NE;
    const int NB1K = (NN + 1023) / 1024;    // 98

    dim3 tb(32, 32);
    k_transpose<<<dim3(2,4), tb>>>(Win, p_Wint, 128, 64);
    k_transpose<<<dim3(4,4), tb>>>(Wf,  p_Wft, 128, 128);
    k_transpose<<<dim3(4,4), tb>>>(Uf,  p_Uft, 128, 128);
    k_transpose<<<dim3(4,4), tb>>>(Wh,  p_Wht, 128, 128);
    k_transpose<<<dim3(4,4), tb>>>(Uh,  p_Uht, 128, 128);
    k_bounds<<<(NN+255)/256, 256>>>(batch);

    // CSR build (once per call)
    k_zero_deg<<<(NN+255)/256, 256>>>();
    k_hist<<<(NE+255)/256, 256>>>(edst);
    k_scan1<<<NB1K, 1024>>>();
    k_scan2<<<1, 128>>>(NB1K);
    k_scan3<<<(NN+255)/256, 256>>>();
    k_curinit<<<(NN+255)/256, 256>>>();
    k_fill<<<(NE+255)/256, 256>>>(esrc, edst);

    k_input<<<(NN+63)/64, 256, 49152>>>(x, bin);

    for (int step = 0; step < 3; step++){
        k_agg<<<(NN*32 + 255)/256, 256>>>();
        k_dualgemm<0><<<152, 512, SMG>>>(p_m, p_h,  p_Wft, p_Uft, bf, p_fb, p_gb, nullptr, nullptr);
        k_dualgemm<1><<<152, 512, SMG>>>(p_m, p_gb, p_Wht, p_Uht, bh, nullptr, nullptr, p_fb, p_h);
    }

    k_zero_s2s<<<(NG*2*HH + 255)/256, 256>>>();
    for (int step = 0; step < 3; step++){
        k_lstm<<<NG, 512>>>(wih, whh, bih, bhh);
        k_attn<<<NG, 256>>>();
    }
    k_pred<<<NG, 128>>>(wp, bp, out);
}

// round 8
// speedup vs baseline: 1.1979x; 1.1231x over previous
#include <cuda_runtime.h>
#include <cuda_bf16.h>
#include <math.h>
#include <stdint.h>

#define NN 100000
#define NE 640000
#define IND 64
#define HH  128
#define NG  128

typedef unsigned long long u64;

// ---------------- scratch (static device globals) ----------------
__device__ float g_h [NN*HH];
__device__ float g_m [NN*HH];
__device__ float g_fb[NN*HH];
__device__ float g_gb[NN*HH];
__device__ float g_Wint[IND*HH];
__device__ float g_Wft[HH*HH];
__device__ float g_Uft[HH*HH];
__device__ float g_Wht[HH*HH];
__device__ float g_Uht[HH*HH];
__device__ float g_e  [NN];
__device__ int   g_bounds[NG+1];
__device__ float g_hl[NG*HH];
__device__ float g_cl[NG*HH];
__device__ float g_qs[NG*2*HH];
// CSR scratch
__device__ int g_deg[NN];
__device__ int g_off[NN+1];
__device__ int g_csr[NE];
__device__ int g_bsum[128];

__device__ __forceinline__ float sigf(float z)   { return __fdividef(1.f, 1.f + __expf(-z)); }
__device__ __forceinline__ float tanhfast(float z){ return 1.f - __fdividef(2.f, __expf(2.f*z) + 1.f); }

// ---- packed fp32x2 helpers (FFMA2) ----
__device__ __forceinline__ u64 dup2(float a){
    u64 r; asm("mov.b64 %0, {%1, %1};" : "=l"(r) : "f"(a)); return r;
}
__device__ __forceinline__ void ffma2(u64& d, u64 a, u64 b){
    asm("fma.rn.f32x2 %0, %1, %2, %0;" : "+l"(d) : "l"(a), "l"(b));
}
__device__ __forceinline__ float2 unpk(u64 v){
    float2 r; asm("mov.b64 {%0, %1}, %2;" : "=f"(r.x), "=f"(r.y) : "l"(v)); return r;
}

// ---------------- batched transpose of the 5 weight matrices ----------------
// blockIdx.z: 0=Win(128x64) 1=Wf 2=Uf 3=Wh 4=Uh (128x128)
__global__ void k_prep5(const float* __restrict__ Win, const float* __restrict__ Wf,
                        const float* __restrict__ Uf,  const float* __restrict__ Wh,
                        const float* __restrict__ Uh){
    __shared__ float t[32][33];
    int mz = blockIdx.z;
    const float* src; float* dst; int R = 128, C = 128;
    switch (mz){
        case 0: src = Win; dst = g_Wint; C = 64; break;
        case 1: src = Wf;  dst = g_Wft; break;
        case 2: src = Uf;  dst = g_Uft; break;
        case 3: src = Wh;  dst = g_Wht; break;
        default: src = Uh; dst = g_Uht; break;
    }
    int c = blockIdx.x*32 + threadIdx.x;
    int r = blockIdx.y*32 + threadIdx.y;
    if (r < R && c < C) t[threadIdx.y][threadIdx.x] = src[r*C + c];
    __syncthreads();
    int rc = blockIdx.x*32 + threadIdx.y;
    int cc = blockIdx.y*32 + threadIdx.x;
    if (rc < C && cc < R) dst[rc*R + cc] = t[threadIdx.x][threadIdx.y];
}

// ---------------- bounds + zero (deg, s2s state) ----------------
__global__ void k_bounds(const int* __restrict__ batch){
    int i = blockIdx.x*blockDim.x + threadIdx.x;
    if (i < NN) g_deg[i] = 0;
    if (i < NG*HH) { g_hl[i] = 0.f; g_cl[i] = 0.f; }
    if (i < NG*2*HH) g_qs[i] = 0.f;
    if (i >= NN) return;
    int b = batch[i];
    if (i == 0)      { for (int g = 0;    g <= b;  g++) g_bounds[g] = 0; }
    else             { int pb = batch[i-1];
                       for (int g = pb+1; g <= b;  g++) g_bounds[g] = i; }
    if (i == NN-1)   { for (int g = b+1;  g <= NG; g++) g_bounds[g] = NN; }
}

// ---------------- CSR build ----------------
__global__ void k_hist(const int* __restrict__ dst){
    int e = blockIdx.x*blockDim.x + threadIdx.x;
    if (e < NE) atomicAdd(&g_deg[dst[e]], 1);
}
__global__ __launch_bounds__(1024) void k_scan1(){
    __shared__ int sd[1024];
    int t = threadIdx.x, i = blockIdx.x*1024 + t;
    int v = (i < NN) ? g_deg[i] : 0;
    sd[t] = v; __syncthreads();
#pragma unroll
    for (int o = 1; o < 1024; o <<= 1){
        int x = (t >= o) ? sd[t-o] : 0;
        __syncthreads();
        sd[t] += x;
        __syncthreads();
    }
    if (i < NN) g_off[i] = sd[t] - v;
    if (t == 1023) g_bsum[blockIdx.x] = sd[1023];
}
__global__ __launch_bounds__(128) void k_scan2(int nb){
    __shared__ int sd[128];
    int t = threadIdx.x;
    int v = (t < nb) ? g_bsum[t] : 0;
    sd[t] = v; __syncthreads();
#pragma unroll
    for (int o = 1; o < 128; o <<= 1){
        int x = (t >= o) ? sd[t-o] : 0;
        __syncthreads();
        sd[t] += x;
        __syncthreads();
    }
    if (t < nb) g_bsum[t] = sd[t] - v;
}
__global__ void k_scan3(){
    int i = blockIdx.x*blockDim.x + threadIdx.x;
    if (i < NN){ int o = g_off[i] + g_bsum[i >> 10]; g_off[i] = o; g_deg[i] = o; }
    if (i == 0) g_off[NN] = NE;
}
__global__ void k_fill(const int* __restrict__ src, const int* __restrict__ dst){
    int e = blockIdx.x*blockDim.x + threadIdx.x;
    if (e >= NE) return;
    int pos = atomicAdd(&g_deg[dst[e]], 1);
    g_csr[pos] = src[e];
}

// ---------------- aggregation: m[n] = sum_{e in csr[n]} h[src_e] ----------------
__global__ __launch_bounds__(256) void k_agg(){
    int w = (blockIdx.x*blockDim.x + threadIdx.x) >> 5;
    if (w >= NN) return;
    int lane = threadIdx.x & 31;
    int s = __ldg(&g_off[w]), e = __ldg(&g_off[w+1]);
    const float4* h4 = (const float4*)g_h;
    float4 acc = make_float4(0.f,0.f,0.f,0.f);
    int p = s;
    for (; p + 1 < e; p += 2){
        int s0 = __ldg(&g_csr[p]);
        int s1 = __ldg(&g_csr[p+1]);
        float4 v0 = __ldg(h4 + (size_t)s0*32 + lane);
        float4 v1 = __ldg(h4 + (size_t)s1*32 + lane);
        acc.x += v0.x; acc.y += v0.y; acc.z += v0.z; acc.w += v0.w;
        acc.x += v1.x; acc.y += v1.y; acc.z += v1.z; acc.w += v1.w;
    }
    if (p < e){
        int s0 = __ldg(&g_csr[p]);
        float4 v0 = __ldg(h4 + (size_t)s0*32 + lane);
        acc.x += v0.x; acc.y += v0.y; acc.z += v0.z; acc.w += v0.w;
    }
    ((float4*)g_m)[(size_t)w*32 + lane] = acc;
}

// ---------------- input layer (FFMA2) ----------------
__global__ __launch_bounds__(256) void k_input(const float* __restrict__ x,
                                               const float* __restrict__ bin){
    extern __shared__ float sm[];
    float4* Ws4 = (float4*)sm;
    float4* Xs4 = (float4*)(sm + IND*HH);
    int tid = threadIdx.x;
    int jt = tid & 31, nt = tid >> 5;

    const float4* Wg = (const float4*)g_Wint;
#pragma unroll
    for (int i = 0; i < 8; i++) Ws4[tid + i*256] = Wg[tid + i*256];

    int base = blockIdx.x * 64;
    const float4* Xg = (const float4*)x;
#pragma unroll
    for (int i = 0; i < 4; i++){
        int q = tid + i*256;
        int rn = q >> 4, col = q & 15;
        int gn = base + rn;
        Xs4[q] = (gn < NN) ? Xg[gn*16 + col] : make_float4(0.f,0.f,0.f,0.f);
    }
    __syncthreads();

    u64 acc[8][2];
#pragma unroll
    for (int i = 0; i < 8; i++){ acc[i][0] = 0ull; acc[i][1] = 0ull; }

    for (int k = 0; k < IND; k += 4){
        float a[8][4];
#pragma unroll
        for (int i = 0; i < 8; i++){
            float4 t4 = Xs4[(nt*8+i)*16 + (k>>2)];
            a[i][0]=t4.x; a[i][1]=t4.y; a[i][2]=t4.z; a[i][3]=t4.w;
        }
#pragma unroll
        for (int kk = 0; kk < 4; kk++){
            ulonglong2 wv = ((const ulonglong2*)Ws4)[(k+kk)*32 + jt];
#pragma unroll
            for (int i = 0; i < 8; i++){
                u64 a2 = dup2(a[i][kk]);
                ffma2(acc[i][0], a2, wv.x);
                ffma2(acc[i][1], a2, wv.y);
            }
        }
    }
    float4 bb = ((const float4*)bin)[jt];
#pragma unroll
    for (int i = 0; i < 8; i++){
        int n = base + nt*8 + i;
        if (n < NN){
            float2 z01 = unpk(acc[i][0]);
            float2 z23 = unpk(acc[i][1]);
            float4 o;
            o.x = fmaxf(z01.x+bb.x, 0.f);
            o.y = fmaxf(z01.y+bb.y, 0.f);
            o.z = fmaxf(z23.x+bb.z, 0.f);
            o.w = fmaxf(z23.y+bb.w, 0.f);
            ((float4*)g_h)[n*32 + jt] = o;
        }
    }
}

// ---------------- dual GEMM (FFMA2, 256 threads, 8n x 4j, reg-prefetch) ----------------
// z = A@Wt + B@Ut + bias (K=2x128). MODE 0: f=sigmoid(z)->O1, g=f*h->O2.
// MODE 1: Hb = (1-Fb)*Hb + Fb*tanh(z) in place. Persistent grid, 192KB smem.
#define SMG ((HH*HH*2 + 64*HH*2) * 4)
template<int MODE>
__global__ __launch_bounds__(256, 1) void k_dualgemm(
    const float* __restrict__ A, const float* __restrict__ B,
    const float* __restrict__ Wt, const float* __restrict__ Ut,
    const float* __restrict__ bias,
    float* __restrict__ O1, float* __restrict__ O2,
    const float* __restrict__ Fb, float* __restrict__ Hb)
{
    extern __shared__ float sm[];
    float4* Ws4 = (float4*)sm;                       // 4096 f4 (k-major)
    float4* Us4 = (float4*)(sm + HH*HH);             // 4096 f4
    float4* As4 = (float4*)(sm + 2*HH*HH);           // 2048 f4
    float4* Bs4 = (float4*)(sm + 2*HH*HH + 64*HH);   // 2048 f4
    int tid = threadIdx.x;
    int jt = tid & 31, nt = tid >> 5;

    const float4* Wg = (const float4*)Wt;
    const float4* Ug = (const float4*)Ut;
#pragma unroll
    for (int i = 0; i < 16; i++){
        Ws4[tid + i*256] = Wg[tid + i*256];
        Us4[tid + i*256] = Ug[tid + i*256];
    }
    float4 bb = ((const float4*)bias)[jt];
    const float4* Ag = (const float4*)A;
    const float4* Bg = (const float4*)B;

    int ntiles = (NN + 63) >> 6;
    int rn0 = tid >> 5, col0 = tid & 31;   // prefetch slot mapping: q = tid + i*256

    float4 pa[8], pb[8];
    // prefetch first tile
    {
        int base = blockIdx.x << 6;
#pragma unroll
        for (int i = 0; i < 8; i++){
            int rn = rn0 + i*8;
            int gn = base + rn;
            if (gn < NN){ pa[i] = __ldg(Ag + (size_t)gn*32 + col0); pb[i] = __ldg(Bg + (size_t)gn*32 + col0); }
            else        { float4 z = make_float4(0.f,0.f,0.f,0.f); pa[i] = z; pb[i] = z; }
        }
    }

    for (int tile = blockIdx.x; tile < ntiles; tile += gridDim.x){
        int base = tile << 6;
        __syncthreads();      // prior tile's smem reads complete
#pragma unroll
        for (int i = 0; i < 8; i++){
            As4[tid + i*256] = pa[i];
            Bs4[tid + i*256] = pb[i];
        }
        __syncthreads();

        // issue next tile's loads (consumed next iteration)
        int ntile = tile + gridDim.x;
        if (ntile < ntiles){
            int nb = ntile << 6;
#pragma unroll
            for (int i = 0; i < 8; i++){
                int gn = nb + rn0 + i*8;
                if (gn < NN){ pa[i] = __ldg(Ag + (size_t)gn*32 + col0); pb[i] = __ldg(Bg + (size_t)gn*32 + col0); }
                else        { float4 z = make_float4(0.f,0.f,0.f,0.f); pa[i] = z; pb[i] = z; }
            }
        }

        u64 acc[8][2];
#pragma unroll
        for (int i = 0; i < 8; i++){ acc[i][0] = 0ull; acc[i][1] = 0ull; }

        for (int k = 0; k < HH; k += 4){
            float a[8][4], b[8][4];
#pragma unroll
            for (int i = 0; i < 8; i++){
                float4 ta = As4[(nt*8+i)*32 + (k>>2)];
                float4 tb = Bs4[(nt*8+i)*32 + (k>>2)];
                a[i][0]=ta.x; a[i][1]=ta.y; a[i][2]=ta.z; a[i][3]=ta.w;
                b[i][0]=tb.x; b[i][1]=tb.y; b[i][2]=tb.z; b[i][3]=tb.w;
            }
#pragma unroll
            for (int kk = 0; kk < 4; kk++){
                ulonglong2 wv = ((const ulonglong2*)Ws4)[(k+kk)*32 + jt];
                ulonglong2 uv = ((const ulonglong2*)Us4)[(k+kk)*32 + jt];
#pragma unroll
                for (int i = 0; i < 8; i++){
                    u64 a2 = dup2(a[i][kk]);
                    u64 b2 = dup2(b[i][kk]);
                    ffma2(acc[i][0], a2, wv.x);
                    ffma2(acc[i][1], a2, wv.y);
                    ffma2(acc[i][0], b2, uv.x);
                    ffma2(acc[i][1], b2, uv.y);
                }
            }
        }

#pragma unroll
        for (int i = 0; i < 8; i++){
            int n = base + nt*8 + i;
            if (n < NN){
                float2 z01 = unpk(acc[i][0]);
                float2 z23 = unpk(acc[i][1]);
                float z0 = z01.x+bb.x, z1 = z01.y+bb.y;
                float z2 = z23.x+bb.z, z3 = z23.y+bb.w;
                if (MODE == 0){
                    float f0 = sigf(z0), f1 = sigf(z1), f2 = sigf(z2), f3 = sigf(z3);
                    float4 hv = Bs4[(nt*8+i)*32 + jt];
                    ((float4*)O1)[(size_t)n*32 + jt] = make_float4(f0, f1, f2, f3);
                    ((float4*)O2)[(size_t)n*32 + jt] = make_float4(f0*hv.x, f1*hv.y, f2*hv.z, f3*hv.w);
                } else {
                    float4 fv = ((const float4*)Fb)[(size_t)n*32 + jt];
                    float4 hv = ((const float4*)Hb)[(size_t)n*32 + jt];
                    float4 o;
                    o.x = (1.f-fv.x)*hv.x + fv.x*tanhfast(z0);
                    o.y = (1.f-fv.y)*hv.y + fv.y*tanhfast(z1);
                    o.z = (1.f-fv.z)*hv.z + fv.z*tanhfast(z2);
                    o.w = (1.f-fv.w)*hv.w + fv.w*tanhfast(z3);
                    ((float4*)Hb)[(size_t)n*32 + jt] = o;
                }
            }
        }
    }
}

// ---------------- Set2Set LSTM ----------------
__global__ __launch_bounds__(512) void k_lstm(const float* __restrict__ wih,
                                              const float* __restrict__ whh,
                                              const float* __restrict__ bih,
                                              const float* __restrict__ bhh){
    __shared__ float qs[2*HH];
    __shared__ float hs[HH];
    __shared__ float gt[4*HH];
    int g = blockIdx.x, t = threadIdx.x;
    if (t < 2*HH) qs[t] = g_qs[g*2*HH + t];
    if (t < HH)   hs[t] = g_hl[g*HH + t];
    __syncthreads();

    float acc = bih[t] + bhh[t];
    const float4* wr  = (const float4*)(wih + t*2*HH);
    const float4* qs4 = (const float4*)qs;
#pragma unroll 8
    for (int k = 0; k < 64; k++){
        float4 w = wr[k], q = qs4[k];
        acc += w.x*q.x + w.y*q.y + w.z*q.z + w.w*q.w;
    }
    const float4* hr  = (const float4*)(whh + t*HH);
    const float4* hs4 = (const float4*)hs;
#pragma unroll 8
    for (int k = 0; k < 32; k++){
        float4 w = hr[k], q = hs4[k];
        acc += w.x*q.x + w.y*q.y + w.z*q.z + w.w*q.w;
    }
    gt[t] = acc;
    __syncthreads();

    if (t < HH){
        float ig = gt[t], fg = gt[HH+t], gg = gt[2*HH+t], og = gt[3*HH+t];
        float c = sigf(fg)*g_cl[g*HH+t] + sigf(ig)*tanhfast(gg);
        g_cl[g*HH+t] = c;
        g_hl[g*HH+t] = sigf(og)*tanhfast(c);
    }
}

// ---------------- Set2Set attention ----------------
__global__ __launch_bounds__(256) void k_attn(){
    __shared__ float q[HH];
    __shared__ float red[8];
    __shared__ float rp[8][HH];
    int g = blockIdx.x, t = threadIdx.x, wid = t >> 5, lane = t & 31;
    int s = g_bounds[g], e = g_bounds[g+1];

    if (t < HH){ float qv = g_hl[g*HH + t]; q[t] = qv; g_qs[g*2*HH + t] = qv; }
    __syncthreads();

    const float4* h4 = (const float4*)g_h;
    float4 q4 = ((float4*)q)[lane];

    float lmax = -3.4e38f;
    for (int n = s + wid; n < e; n += 8){
        float4 x4 = h4[n*32 + lane];
        float p = x4.x*q4.x + x4.y*q4.y + x4.z*q4.z + x4.w*q4.w;
#pragma unroll
        for (int o = 16; o; o >>= 1) p += __shfl_xor_sync(0xffffffffu, p, o);
        if (lane == 0) g_e[n] = p;
        lmax = fmaxf(lmax, p);
    }
    if (lane == 0) red[wid] = lmax;
    __syncthreads();
    float emax = -3.4e38f;
#pragma unroll
    for (int w = 0; w < 8; w++) emax = fmaxf(emax, red[w]);
    __syncthreads();

    float lsum = 0.f;
    for (int n = s + t; n < e; n += 256){
        float w = __expf(g_e[n] - emax);
        g_e[n] = w;
        lsum += w;
    }
#pragma unroll
    for (int o = 16; o; o >>= 1) lsum += __shfl_xor_sync(0xffffffffu, lsum, o);
    if (lane == 0) red[wid] = lsum;
    __syncthreads();
    float denom = 0.f;
#pragma unroll
    for (int w = 0; w < 8; w++) denom += red[w];

    float4 racc = make_float4(0.f,0.f,0.f,0.f);
    for (int n = s + wid; n < e; n += 8){
        float coef = g_e[n];
        float4 x4 = h4[n*32 + lane];
        racc.x += coef*x4.x; racc.y += coef*x4.y;
        racc.z += coef*x4.z; racc.w += coef*x4.w;
    }
    ((float4*)rp[wid])[lane] = racc;
    __syncthreads();
    if (t < HH){
        float r = 0.f;
#pragma unroll
        for (int w = 0; w < 8; w++) r += rp[w][t];
        r = (e > s) ? (r / denom) : 0.f;
        g_qs[g*2*HH + HH + t] = r;
    }
}

// ---------------- prediction ----------------
__global__ __launch_bounds__(128) void k_pred(const float* __restrict__ wp,
                                              const float* __restrict__ bp,
                                              float* __restrict__ out){
    __shared__ float red[4];
    int g = blockIdx.x, t = threadIdx.x;
    float p = g_qs[g*256 + t]*wp[t] + g_qs[g*256 + 128 + t]*wp[128 + t];
#pragma unroll
    for (int o = 16; o; o >>= 1) p += __shfl_xor_sync(0xffffffffu, p, o);
    if ((t & 31) == 0) red[t >> 5] = p;
    __syncthreads();
    if (t == 0) out[g] = red[0] + red[1] + red[2] + red[3] + bp[0];
}

// ---------------- launcher ----------------
extern "C" void kernel_launch(void* const* d_in, const int* in_sizes, int n_in,
                              void* d_out, int out_size){
    const float* x    = (const float*)d_in[0];
    const int*   ei   = (const int*)  d_in[1];
    const int*   batch= (const int*)  d_in[2];
    const float* Win  = (const float*)d_in[3];
    const float* bin  = (const float*)d_in[4];
    const float* Wf   = (const float*)d_in[5];
    const float* Uf   = (const float*)d_in[6];
    const float* bf   = (const float*)d_in[7];
    const float* Wh   = (const float*)d_in[8];
    const float* Uh   = (const float*)d_in[9];
    const float* bh   = (const float*)d_in[10];
    const float* wih  = (const float*)d_in[11];
    const float* whh  = (const float*)d_in[12];
    const float* bih  = (const float*)d_in[13];
    const float* bhh  = (const float*)d_in[14];
    const float* wp   = (const float*)d_in[15];
    const float* bp   = (const float*)d_in[16];
    float* out = (float*)d_out;

    float *p_m, *p_h, *p_fb, *p_gb, *p_Wft, *p_Uft, *p_Wht, *p_Uht;
    cudaGetSymbolAddress((void**)&p_m,    g_m);
    cudaGetSymbolAddress((void**)&p_h,    g_h);
    cudaGetSymbolAddress((void**)&p_fb,   g_fb);
    cudaGetSymbolAddress((void**)&p_gb,   g_gb);
    cudaGetSymbolAddress((void**)&p_Wft,  g_Wft);
    cudaGetSymbolAddress((void**)&p_Uft,  g_Uft);
    cudaGetSymbolAddress((void**)&p_Wht,  g_Wht);
    cudaGetSymbolAddress((void**)&p_Uht,  g_Uht);

    cudaFuncSetAttribute(k_dualgemm<0>, cudaFuncAttributeMaxDynamicSharedMemorySize, SMG);
    cudaFuncSetAttribute(k_dualgemm<1>, cudaFuncAttributeMaxDynamicSharedMemorySize, SMG);
    cudaFuncSetAttribute(k_input,       cudaFuncAttributeMaxDynamicSharedMemorySize, 49152);

    const int* esrc = ei;
    const int* edst = ei + NE;
    const int NB1K = (NN + 1023) / 1024;

    k_prep5<<<dim3(4,4,5), dim3(32,32)>>>(Win, Wf, Uf, Wh, Uh);
    k_bounds<<<(NN+255)/256, 256>>>(batch);

    // CSR build
    k_hist<<<(NE+255)/256, 256>>>(edst);
    k_scan1<<<NB1K, 1024>>>();
    k_scan2<<<1, 128>>>(NB1K);
    k_scan3<<<(NN+255)/256, 256>>>();
    k_fill<<<(NE+255)/256, 256>>>(esrc, edst);

    k_input<<<(NN+63)/64, 256, 49152>>>(x, bin);

    for (int step = 0; step < 3; step++){
        k_agg<<<(NN*32 + 255)/256, 256>>>();
        k_dualgemm<0><<<152, 256, SMG>>>(p_m, p_h,  p_Wft, p_Uft, bf, p_fb, p_gb, nullptr, nullptr);
        k_dualgemm<1><<<152, 256, SMG>>>(p_m, p_gb, p_Wht, p_Uht, bh, nullptr, nullptr, p_fb, p_h);
    }

    for (int step = 0; step < 3; step++){
        k_lstm<<<NG, 512>>>(wih, whh, bih, bhh);
        k_attn<<<NG, 256>>>();
    }
    k_pred<<<NG, 128>>>(wp, bp, out);
}

// round 9
// speedup vs baseline: 1.2354x; 1.0314x over previous
#include <cuda_runtime.h>
#include <cuda_bf16.h>
#include <math.h>
#include <stdint.h>

#define NN 100000
#define NE 640000
#define IND 64
#define HH  128
#define NG  128

typedef unsigned long long u64;

// ---------------- scratch (static device globals) ----------------
__device__ float g_h [NN*HH];
__device__ float g_m [NN*HH];
__device__ float g_fb[NN*HH];
__device__ float g_gb[NN*HH];
__device__ float g_Wint[IND*HH];
__device__ float g_Wft[HH*HH];
__device__ float g_Uft[HH*HH];
__device__ float g_Wht[HH*HH];
__device__ float g_Uht[HH*HH];
__device__ float g_e  [NN];
__device__ int   g_bounds[NG+1];
// CSR scratch
__device__ int g_deg[NN];
__device__ int g_off[NN+1];
__device__ int g_csr[NE];
__device__ int g_bsum[128];

__device__ __forceinline__ float sigf(float z)   { return __fdividef(1.f, 1.f + __expf(-z)); }
__device__ __forceinline__ float tanhfast(float z){ return 1.f - __fdividef(2.f, __expf(2.f*z) + 1.f); }

// ---- packed fp32x2 helpers (FFMA2) ----
__device__ __forceinline__ u64 dup2(float a){
    u64 r; asm("mov.b64 %0, {%1, %1};" : "=l"(r) : "f"(a)); return r;
}
__device__ __forceinline__ void ffma2(u64& d, u64 a, u64 b){
    asm("fma.rn.f32x2 %0, %1, %2, %0;" : "+l"(d) : "l"(a), "l"(b));
}
__device__ __forceinline__ float2 unpk(u64 v){
    float2 r; asm("mov.b64 {%0, %1}, %2;" : "=f"(r.x), "=f"(r.y) : "l"(v)); return r;
}

// ---------------- batched transpose of the 5 weight matrices ----------------
__global__ void k_prep5(const float* __restrict__ Win, const float* __restrict__ Wf,
                        const float* __restrict__ Uf,  const float* __restrict__ Wh,
                        const float* __restrict__ Uh){
    __shared__ float t[32][33];
    int mz = blockIdx.z;
    const float* src; float* dst; int R = 128, C = 128;
    switch (mz){
        case 0: src = Win; dst = g_Wint; C = 64; break;
        case 1: src = Wf;  dst = g_Wft; break;
        case 2: src = Uf;  dst = g_Uft; break;
        case 3: src = Wh;  dst = g_Wht; break;
        default: src = Uh; dst = g_Uht; break;
    }
    int c = blockIdx.x*32 + threadIdx.x;
    int r = blockIdx.y*32 + threadIdx.y;
    if (r < R && c < C) t[threadIdx.y][threadIdx.x] = src[r*C + c];
    __syncthreads();
    int rc = blockIdx.x*32 + threadIdx.y;
    int cc = blockIdx.y*32 + threadIdx.x;
    if (rc < C && cc < R) dst[rc*R + cc] = t[threadIdx.x][threadIdx.y];
}

// ---------------- bounds + zero deg ----------------
__global__ void k_bounds(const int* __restrict__ batch){
    int i = blockIdx.x*blockDim.x + threadIdx.x;
    if (i < NN) g_deg[i] = 0;
    if (i >= NN) return;
    int b = batch[i];
    if (i == 0)      { for (int g = 0;    g <= b;  g++) g_bounds[g] = 0; }
    else             { int pb = batch[i-1];
                       for (int g = pb+1; g <= b;  g++) g_bounds[g] = i; }
    if (i == NN-1)   { for (int g = b+1;  g <= NG; g++) g_bounds[g] = NN; }
}

// ---------------- CSR build ----------------
__global__ void k_hist(const int* __restrict__ dst){
    int e = blockIdx.x*blockDim.x + threadIdx.x;
    if (e < NE) atomicAdd(&g_deg[dst[e]], 1);
}
__global__ __launch_bounds__(1024) void k_scan1(){
    __shared__ int sd[1024];
    int t = threadIdx.x, i = blockIdx.x*1024 + t;
    int v = (i < NN) ? g_deg[i] : 0;
    sd[t] = v; __syncthreads();
#pragma unroll
    for (int o = 1; o < 1024; o <<= 1){
        int x = (t >= o) ? sd[t-o] : 0;
        __syncthreads();
        sd[t] += x;
        __syncthreads();
    }
    if (i < NN) g_off[i] = sd[t] - v;
    if (t == 1023) g_bsum[blockIdx.x] = sd[1023];
}
__global__ __launch_bounds__(128) void k_scan2(int nb){
    __shared__ int sd[128];
    int t = threadIdx.x;
    int v = (t < nb) ? g_bsum[t] : 0;
    sd[t] = v; __syncthreads();
#pragma unroll
    for (int o = 1; o < 128; o <<= 1){
        int x = (t >= o) ? sd[t-o] : 0;
        __syncthreads();
        sd[t] += x;
        __syncthreads();
    }
    if (t < nb) g_bsum[t] = sd[t] - v;
}
__global__ void k_scan3(){
    int i = blockIdx.x*blockDim.x + threadIdx.x;
    if (i < NN){ int o = g_off[i] + g_bsum[i >> 10]; g_off[i] = o; g_deg[i] = o; }
    if (i == 0) g_off[NN] = NE;
}
__global__ void k_fill(const int* __restrict__ src, const int* __restrict__ dst){
    int e = blockIdx.x*blockDim.x + threadIdx.x;
    if (e >= NE) return;
    int pos = atomicAdd(&g_deg[dst[e]], 1);
    g_csr[pos] = src[e];
}

// ---------------- aggregation: m[n] = sum_{e in csr[n]} h[src_e] ----------------
__global__ __launch_bounds__(256) void k_agg(){
    int w = (blockIdx.x*blockDim.x + threadIdx.x) >> 5;
    if (w >= NN) return;
    int lane = threadIdx.x & 31;
    int s = __ldg(&g_off[w]), e = __ldg(&g_off[w+1]);
    const float4* h4 = (const float4*)g_h;
    float4 acc = make_float4(0.f,0.f,0.f,0.f);
    int p = s;
    for (; p + 1 < e; p += 2){
        int s0 = __ldg(&g_csr[p]);
        int s1 = __ldg(&g_csr[p+1]);
        float4 v0 = __ldg(h4 + (size_t)s0*32 + lane);
        float4 v1 = __ldg(h4 + (size_t)s1*32 + lane);
        acc.x += v0.x; acc.y += v0.y; acc.z += v0.z; acc.w += v0.w;
        acc.x += v1.x; acc.y += v1.y; acc.z += v1.z; acc.w += v1.w;
    }
    if (p < e){
        int s0 = __ldg(&g_csr[p]);
        float4 v0 = __ldg(h4 + (size_t)s0*32 + lane);
        acc.x += v0.x; acc.y += v0.y; acc.z += v0.z; acc.w += v0.w;
    }
    ((float4*)g_m)[(size_t)w*32 + lane] = acc;
}

// ---------------- input layer (FFMA2) ----------------
__global__ __launch_bounds__(256) void k_input(const float* __restrict__ x,
                                               const float* __restrict__ bin){
    extern __shared__ float sm[];
    float4* Ws4 = (float4*)sm;
    float4* Xs4 = (float4*)(sm + IND*HH);
    int tid = threadIdx.x;
    int jt = tid & 31, nt = tid >> 5;

    const float4* Wg = (const float4*)g_Wint;
#pragma unroll
    for (int i = 0; i < 8; i++) Ws4[tid + i*256] = Wg[tid + i*256];

    int base = blockIdx.x * 64;
    const float4* Xg = (const float4*)x;
#pragma unroll
    for (int i = 0; i < 4; i++){
        int q = tid + i*256;
        int rn = q >> 4, col = q & 15;
        int gn = base + rn;
        Xs4[q] = (gn < NN) ? Xg[gn*16 + col] : make_float4(0.f,0.f,0.f,0.f);
    }
    __syncthreads();

    u64 acc[8][2];
#pragma unroll
    for (int i = 0; i < 8; i++){ acc[i][0] = 0ull; acc[i][1] = 0ull; }

    for (int k = 0; k < IND; k += 4){
        float a[8][4];
#pragma unroll
        for (int i = 0; i < 8; i++){
            float4 t4 = Xs4[(nt*8+i)*16 + (k>>2)];
            a[i][0]=t4.x; a[i][1]=t4.y; a[i][2]=t4.z; a[i][3]=t4.w;
        }
#pragma unroll
        for (int kk = 0; kk < 4; kk++){
            ulonglong2 wv = ((const ulonglong2*)Ws4)[(k+kk)*32 + jt];
#pragma unroll
            for (int i = 0; i < 8; i++){
                u64 a2 = dup2(a[i][kk]);
                ffma2(acc[i][0], a2, wv.x);
                ffma2(acc[i][1], a2, wv.y);
            }
        }
    }
    float4 bb = ((const float4*)bin)[jt];
#pragma unroll
    for (int i = 0; i < 8; i++){
        int n = base + nt*8 + i;
        if (n < NN){
            float2 z01 = unpk(acc[i][0]);
            float2 z23 = unpk(acc[i][1]);
            float4 o;
            o.x = fmaxf(z01.x+bb.x, 0.f);
            o.y = fmaxf(z01.y+bb.y, 0.f);
            o.z = fmaxf(z23.x+bb.z, 0.f);
            o.w = fmaxf(z23.y+bb.w, 0.f);
            ((float4*)g_h)[n*32 + jt] = o;
        }
    }
}

// ---------------- dual GEMM (FFMA2, 256 threads, 8n x 4j, reg-prefetch) ----------------
#define SMG ((HH*HH*2 + 64*HH*2) * 4)
template<int MODE>
__global__ __launch_bounds__(256, 1) void k_dualgemm(
    const float* __restrict__ A, const float* __restrict__ B,
    const float* __restrict__ Wt, const float* __restrict__ Ut,
    const float* __restrict__ bias,
    float* __restrict__ O1, float* __restrict__ O2,
    const float* __restrict__ Fb, float* __restrict__ Hb)
{
    extern __shared__ float sm[];
    float4* Ws4 = (float4*)sm;
    float4* Us4 = (float4*)(sm + HH*HH);
    float4* As4 = (float4*)(sm + 2*HH*HH);
    float4* Bs4 = (float4*)(sm + 2*HH*HH + 64*HH);
    int tid = threadIdx.x;
    int jt = tid & 31, nt = tid >> 5;

    const float4* Wg = (const float4*)Wt;
    const float4* Ug = (const float4*)Ut;
#pragma unroll
    for (int i = 0; i < 16; i++){
        Ws4[tid + i*256] = Wg[tid + i*256];
        Us4[tid + i*256] = Ug[tid + i*256];
    }
    float4 bb = ((const float4*)bias)[jt];
    const float4* Ag = (const float4*)A;
    const float4* Bg = (const float4*)B;

    int ntiles = (NN + 63) >> 6;
    int rn0 = tid >> 5, col0 = tid & 31;

    float4 pa[8], pb[8];
    {
        int base = blockIdx.x << 6;
#pragma unroll
        for (int i = 0; i < 8; i++){
            int gn = base + rn0 + i*8;
            if (gn < NN){ pa[i] = __ldg(Ag + (size_t)gn*32 + col0); pb[i] = __ldg(Bg + (size_t)gn*32 + col0); }
            else        { float4 z = make_float4(0.f,0.f,0.f,0.f); pa[i] = z; pb[i] = z; }
        }
    }

    for (int tile = blockIdx.x; tile < ntiles; tile += gridDim.x){
        int base = tile << 6;
        __syncthreads();
#pragma unroll
        for (int i = 0; i < 8; i++){
            As4[tid + i*256] = pa[i];
            Bs4[tid + i*256] = pb[i];
        }
        __syncthreads();

        int ntile = tile + gridDim.x;
        if (ntile < ntiles){
            int nb = ntile << 6;
#pragma unroll
            for (int i = 0; i < 8; i++){
                int gn = nb + rn0 + i*8;
                if (gn < NN){ pa[i] = __ldg(Ag + (size_t)gn*32 + col0); pb[i] = __ldg(Bg + (size_t)gn*32 + col0); }
                else        { float4 z = make_float4(0.f,0.f,0.f,0.f); pa[i] = z; pb[i] = z; }
            }
        }

        u64 acc[8][2];
#pragma unroll
        for (int i = 0; i < 8; i++){ acc[i][0] = 0ull; acc[i][1] = 0ull; }

        for (int k = 0; k < HH; k += 4){
            float a[8][4], b[8][4];
#pragma unroll
            for (int i = 0; i < 8; i++){
                float4 ta = As4[(nt*8+i)*32 + (k>>2)];
                float4 tb = Bs4[(nt*8+i)*32 + (k>>2)];
                a[i][0]=ta.x; a[i][1]=ta.y; a[i][2]=ta.z; a[i][3]=ta.w;
                b[i][0]=tb.x; b[i][1]=tb.y; b[i][2]=tb.z; b[i][3]=tb.w;
            }
#pragma unroll
            for (int kk = 0; kk < 4; kk++){
                ulonglong2 wv = ((const ulonglong2*)Ws4)[(k+kk)*32 + jt];
                ulonglong2 uv = ((const ulonglong2*)Us4)[(k+kk)*32 + jt];
#pragma unroll
                for (int i = 0; i < 8; i++){
                    u64 a2 = dup2(a[i][kk]);
                    u64 b2 = dup2(b[i][kk]);
                    ffma2(acc[i][0], a2, wv.x);
                    ffma2(acc[i][1], a2, wv.y);
                    ffma2(acc[i][0], b2, uv.x);
                    ffma2(acc[i][1], b2, uv.y);
                }
            }
        }

#pragma unroll
        for (int i = 0; i < 8; i++){
            int n = base + nt*8 + i;
            if (n < NN){
                float2 z01 = unpk(acc[i][0]);
                float2 z23 = unpk(acc[i][1]);
                float z0 = z01.x+bb.x, z1 = z01.y+bb.y;
                float z2 = z23.x+bb.z, z3 = z23.y+bb.w;
                if (MODE == 0){
                    float f0 = sigf(z0), f1 = sigf(z1), f2 = sigf(z2), f3 = sigf(z3);
                    float4 hv = Bs4[(nt*8+i)*32 + jt];
                    ((float4*)O1)[(size_t)n*32 + jt] = make_float4(f0, f1, f2, f3);
                    ((float4*)O2)[(size_t)n*32 + jt] = make_float4(f0*hv.x, f1*hv.y, f2*hv.z, f3*hv.w);
                } else {
                    float4 fv = ((const float4*)Fb)[(size_t)n*32 + jt];
                    float4 hv = ((const float4*)Hb)[(size_t)n*32 + jt];
                    float4 o;
                    o.x = (1.f-fv.x)*hv.x + fv.x*tanhfast(z0);
                    o.y = (1.f-fv.y)*hv.y + fv.y*tanhfast(z1);
                    o.z = (1.f-fv.z)*hv.z + fv.z*tanhfast(z2);
                    o.w = (1.f-fv.w)*hv.w + fv.w*tanhfast(z3);
                    ((float4*)Hb)[(size_t)n*32 + jt] = o;
                }
            }
        }
    }
}

// ---------------- fused Set2Set (3 steps LSTM+attn) + prediction ----------------
// one block per graph; q_star/h/c live in SMEM across steps.
__global__ __launch_bounds__(256) void k_s2s(
    const float* __restrict__ wih, const float* __restrict__ whh,
    const float* __restrict__ bih, const float* __restrict__ bhh,
    const float* __restrict__ wp,  const float* __restrict__ bp,
    float* __restrict__ out)
{
    __shared__ __align__(16) float qs[2*HH];
    __shared__ __align__(16) float hl[HH];
    __shared__ __align__(16) float cl[HH];
    __shared__ float gt[4*HH];
    __shared__ float red[8];
    __shared__ __align__(16) float rp[8][HH];

    int g = blockIdx.x, t = threadIdx.x, wid = t >> 5, lane = t & 31;
    int s = g_bounds[g], e = g_bounds[g+1];
    const float4* h4 = (const float4*)g_h;

    if (t < HH){ hl[t] = 0.f; cl[t] = 0.f; }
    qs[t] = 0.f;
    __syncthreads();

    for (int step = 0; step < 3; step++){
        // ---- LSTM gates: warp-cooperative rows ----
        {
            const float4* qs4 = (const float4*)qs;
            const float4* hl4 = (const float4*)hl;
            float4 q0 = qs4[lane], q1 = qs4[32 + lane];
            float4 hh0 = hl4[lane];
            for (int r = wid*64; r < wid*64 + 64; r++){
                const float4* wr = (const float4*)(wih + (size_t)r*2*HH);
                const float4* hr = (const float4*)(whh + (size_t)r*HH);
                float4 w0 = __ldg(wr + lane);
                float4 w1 = __ldg(wr + 32 + lane);
                float4 h0 = __ldg(hr + lane);
                float p = w0.x*q0.x + w0.y*q0.y + w0.z*q0.z + w0.w*q0.w
                        + w1.x*q1.x + w1.y*q1.y + w1.z*q1.z + w1.w*q1.w
                        + h0.x*hh0.x + h0.y*hh0.y + h0.z*hh0.z + h0.w*hh0.w;
#pragma unroll
                for (int o = 16; o; o >>= 1) p += __shfl_xor_sync(0xffffffffu, p, o);
                if (lane == 0) gt[r] = p + __ldg(&bih[r]) + __ldg(&bhh[r]);
            }
        }
        __syncthreads();
        if (t < HH){
            float c = sigf(gt[HH+t])*cl[t] + sigf(gt[t])*tanhfast(gt[2*HH+t]);
            cl[t] = c;
            float hv = sigf(gt[3*HH+t])*tanhfast(c);
            hl[t] = hv;
            qs[t] = hv;              // q_star first half = q
        }
        __syncthreads();

        // ---- attention pass 1: e[n]=dot(h[n],q), block max; 4 nodes/warp-iter ----
        float4 q4 = ((const float4*)hl)[lane];
        float lmax = -3.4e38f;
        for (int b = s + wid*4; b < e; b += 32){
            float p[4];
#pragma unroll
            for (int j = 0; j < 4; j++){
                if (b + j < e){
                    float4 x = __ldg(h4 + (size_t)(b+j)*32 + lane);
                    p[j] = x.x*q4.x + x.y*q4.y + x.z*q4.z + x.w*q4.w;
                } else p[j] = 0.f;
            }
#pragma unroll
            for (int o = 16; o; o >>= 1){
#pragma unroll
                for (int j = 0; j < 4; j++) p[j] += __shfl_xor_sync(0xffffffffu, p[j], o);
            }
#pragma unroll
            for (int j = 0; j < 4; j++){
                if (b + j < e){
                    if (lane == 0) g_e[b+j] = p[j];
                    lmax = fmaxf(lmax, p[j]);
                }
            }
        }
        if (lane == 0) red[wid] = lmax;
        __syncthreads();
        float emax = -3.4e38f;
#pragma unroll
        for (int w = 0; w < 8; w++) emax = fmaxf(emax, red[w]);
        __syncthreads();

        // ---- pass 2: w=exp(e-emax), block sum ----
        float lsum = 0.f;
        for (int n = s + t; n < e; n += 256){
            float w = __expf(g_e[n] - emax);
            g_e[n] = w;
            lsum += w;
        }
#pragma unroll
        for (int o = 16; o; o >>= 1) lsum += __shfl_xor_sync(0xffffffffu, lsum, o);
        if (lane == 0) red[wid] = lsum;
        __syncthreads();
        float denom = 0.f;
#pragma unroll
        for (int w = 0; w < 8; w++) denom += red[w];

        // ---- pass 3: r = sum w[n]*h[n]/denom; 4 nodes/warp-iter ----
        float4 racc = make_float4(0.f,0.f,0.f,0.f);
        for (int b = s + wid*4; b < e; b += 32){
#pragma unroll
            for (int j = 0; j < 4; j++){
                if (b + j < e){
                    float coef = __ldg(&g_e[b+j]);
                    float4 x = __ldg(h4 + (size_t)(b+j)*32 + lane);
                    racc.x += coef*x.x; racc.y += coef*x.y;
                    racc.z += coef*x.z; racc.w += coef*x.w;
                }
            }
        }
        ((float4*)rp[wid])[lane] = racc;
        __syncthreads();
        if (t < HH){
            float r = 0.f;
#pragma unroll
            for (int w = 0; w < 8; w++) r += rp[w][t];
            qs[HH + t] = (e > s) ? (r / denom) : 0.f;
        }
        __syncthreads();
    }

    // ---- prediction: out[g] = dot(q_star, wp) + bp ----
    float p = qs[t] * __ldg(&wp[t]);
#pragma unroll
    for (int o = 16; o; o >>= 1) p += __shfl_xor_sync(0xffffffffu, p, o);
    if (lane == 0) red[wid] = p;
    __syncthreads();
    if (t == 0){
        float r = 0.f;
#pragma unroll
        for (int w = 0; w < 8; w++) r += red[w];
        out[g] = r + __ldg(&bp[0]);
    }
}

// ---------------- launcher ----------------
extern "C" void kernel_launch(void* const* d_in, const int* in_sizes, int n_in,
                              void* d_out, int out_size){
    const float* x    = (const float*)d_in[0];
    const int*   ei   = (const int*)  d_in[1];
    const int*   batch= (const int*)  d_in[2];
    const float* Win  = (const float*)d_in[3];
    const float* bin  = (const float*)d_in[4];
    const float* Wf   = (const float*)d_in[5];
    const float* Uf   = (const float*)d_in[6];
    const float* bf   = (const float*)d_in[7];
    const float* Wh   = (const float*)d_in[8];
    const float* Uh   = (const float*)d_in[9];
    const float* bh   = (const float*)d_in[10];
    const float* wih  = (const float*)d_in[11];
    const float* whh  = (const float*)d_in[12];
    const float* bih  = (const float*)d_in[13];
    const float* bhh  = (const float*)d_in[14];
    const float* wp   = (const float*)d_in[15];
    const float* bp   = (const float*)d_in[16];
    float* out = (float*)d_out;

    float *p_m, *p_h, *p_fb, *p_gb, *p_Wft, *p_Uft, *p_Wht, *p_Uht;
    cudaGetSymbolAddress((void**)&p_m,    g_m);
    cudaGetSymbolAddress((void**)&p_h,    g_h);
    cudaGetSymbolAddress((void**)&p_fb,   g_fb);
    cudaGetSymbolAddress((void**)&p_gb,   g_gb);
    cudaGetSymbolAddress((void**)&p_Wft,  g_Wft);
    cudaGetSymbolAddress((void**)&p_Uft,  g_Uft);
    cudaGetSymbolAddress((void**)&p_Wht,  g_Wht);
    cudaGetSymbolAddress((void**)&p_Uht,  g_Uht);

    cudaFuncSetAttribute(k_dualgemm<0>, cudaFuncAttributeMaxDynamicSharedMemorySize, SMG);
    cudaFuncSetAttribute(k_dualgemm<1>, cudaFuncAttributeMaxDynamicSharedMemorySize, SMG);
    cudaFuncSetAttribute(k_input,       cudaFuncAttributeMaxDynamicSharedMemorySize, 49152);

    const int* esrc = ei;
    const int* edst = ei + NE;
    const int NB1K = (NN + 1023) / 1024;

    k_prep5<<<dim3(4,4,5), dim3(32,32)>>>(Win, Wf, Uf, Wh, Uh);
    k_bounds<<<(NN+255)/256, 256>>>(batch);

    k_hist<<<(NE+255)/256, 256>>>(edst);
    k_scan1<<<NB1K, 1024>>>();
    k_scan2<<<1, 128>>>(NB1K);
    k_scan3<<<(NN+255)/256, 256>>>();
    k_fill<<<(NE+255)/256, 256>>>(esrc, edst);

    k_input<<<(NN+63)/64, 256, 49152>>>(x, bin);

    for (int step = 0; step < 3; step++){
        k_agg<<<(NN*32 + 255)/256, 256>>>();
        k_dualgemm<0><<<152, 256, SMG>>>(p_m, p_h,  p_Wft, p_Uft, bf, p_fb, p_gb, nullptr, nullptr);
        k_dualgemm<1><<<152, 256, SMG>>>(p_m, p_gb, p_Wht, p_Uht, bh, nullptr, nullptr, p_fb, p_h);
    }

    k_s2s<<<NG, 256>>>(wih, whh, bih, bhh, wp, bp, out);
}

// round 10
// speedup vs baseline: 1.3318x; 1.0780x over previous
#include <cuda_runtime.h>
#include <cuda_bf16.h>
#include <math.h>
#include <stdint.h>

#define NN 100000
#define NE 640000
#define IND 64
#define HH  128
#define NG  128

typedef unsigned long long u64;

// ---------------- scratch (static device globals) ----------------
__device__ float g_h [NN*HH];
__device__ float g_m [NN*HH];
__device__ float g_Wint[IND*HH];
__device__ float g_Wft[HH*HH];
__device__ float g_Uft[HH*HH];
__device__ float g_Wht[HH*HH];
__device__ float g_Uht[HH*HH];
__device__ float g_e  [NN];
__device__ int   g_bounds[NG+1];
// CSR scratch
__device__ int g_deg[NN];
__device__ int g_off[NN+1];
__device__ int g_csr[NE];
__device__ int g_bsum[128];

__device__ __forceinline__ float sigf(float z)   { return __fdividef(1.f, 1.f + __expf(-z)); }
__device__ __forceinline__ float tanhfast(float z){ return 1.f - __fdividef(2.f, __expf(2.f*z) + 1.f); }

// ---- packed fp32x2 helpers (FFMA2) ----
__device__ __forceinline__ u64 dup2(float a){
    u64 r; asm("mov.b64 %0, {%1, %1};" : "=l"(r) : "f"(a)); return r;
}
__device__ __forceinline__ void ffma2(u64& d, u64 a, u64 b){
    asm("fma.rn.f32x2 %0, %1, %2, %0;" : "+l"(d) : "l"(a), "l"(b));
}
__device__ __forceinline__ float2 unpk(u64 v){
    float2 r; asm("mov.b64 {%0, %1}, %2;" : "=f"(r.x), "=f"(r.y) : "l"(v)); return r;
}

// ---------------- batched transpose of the 5 weight matrices ----------------
__global__ void k_prep5(const float* __restrict__ Win, const float* __restrict__ Wf,
                        const float* __restrict__ Uf,  const float* __restrict__ Wh,
                        const float* __restrict__ Uh){
    __shared__ float t[32][33];
    int mz = blockIdx.z;
    const float* src; float* dst; int R = 128, C = 128;
    switch (mz){
        case 0: src = Win; dst = g_Wint; C = 64; break;
        case 1: src = Wf;  dst = g_Wft; break;
        case 2: src = Uf;  dst = g_Uft; break;
        case 3: src = Wh;  dst = g_Wht; break;
        default: src = Uh; dst = g_Uht; break;
    }
    int c = blockIdx.x*32 + threadIdx.x;
    int r = blockIdx.y*32 + threadIdx.y;
    if (r < R && c < C) t[threadIdx.y][threadIdx.x] = src[r*C + c];
    __syncthreads();
    int rc = blockIdx.x*32 + threadIdx.y;
    int cc = blockIdx.y*32 + threadIdx.x;
    if (rc < C && cc < R) dst[rc*R + cc] = t[threadIdx.x][threadIdx.y];
}

// ---------------- bounds + zero deg ----------------
__global__ void k_bounds(const int* __restrict__ batch){
    int i = blockIdx.x*blockDim.x + threadIdx.x;
    if (i < NN) g_deg[i] = 0;
    if (i >= NN) return;
    int b = batch[i];
    if (i == 0)      { for (int g = 0;    g <= b;  g++) g_bounds[g] = 0; }
    else             { int pb = batch[i-1];
                       for (int g = pb+1; g <= b;  g++) g_bounds[g] = i; }
    if (i == NN-1)   { for (int g = b+1;  g <= NG; g++) g_bounds[g] = NN; }
}

// ---------------- CSR build ----------------
__global__ void k_hist(const int* __restrict__ dst){
    int e = blockIdx.x*blockDim.x + threadIdx.x;
    if (e < NE) atomicAdd(&g_deg[dst[e]], 1);
}
__global__ __launch_bounds__(1024) void k_scan1(){
    __shared__ int sd[1024];
    int t = threadIdx.x, i = blockIdx.x*1024 + t;
    int v = (i < NN) ? g_deg[i] : 0;
    sd[t] = v; __syncthreads();
#pragma unroll
    for (int o = 1; o < 1024; o <<= 1){
        int x = (t >= o) ? sd[t-o] : 0;
        __syncthreads();
        sd[t] += x;
        __syncthreads();
    }
    if (i < NN) g_off[i] = sd[t] - v;
    if (t == 1023) g_bsum[blockIdx.x] = sd[1023];
}
__global__ __launch_bounds__(128) void k_scan2(int nb){
    __shared__ int sd[128];
    int t = threadIdx.x;
    int v = (t < nb) ? g_bsum[t] : 0;
    sd[t] = v; __syncthreads();
#pragma unroll
    for (int o = 1; o < 128; o <<= 1){
        int x = (t >= o) ? sd[t-o] : 0;
        __syncthreads();
        sd[t] += x;
        __syncthreads();
    }
    if (t < nb) g_bsum[t] = sd[t] - v;
}
__global__ void k_scan3(){
    int i = blockIdx.x*blockDim.x + threadIdx.x;
    if (i < NN){ int o = g_off[i] + g_bsum[i >> 10]; g_off[i] = o; g_deg[i] = o; }
    if (i == 0) g_off[NN] = NE;
}
__global__ void k_fill(const int* __restrict__ src, const int* __restrict__ dst){
    int e = blockIdx.x*blockDim.x + threadIdx.x;
    if (e >= NE) return;
    int pos = atomicAdd(&g_deg[dst[e]], 1);
    g_csr[pos] = src[e];
}

// ---------------- aggregation: m[n] = sum_{e in csr[n]} h[src_e] ----------------
__global__ __launch_bounds__(256) void k_agg(){
    int w = (blockIdx.x*blockDim.x + threadIdx.x) >> 5;
    if (w >= NN) return;
    int lane = threadIdx.x & 31;
    int s = __ldg(&g_off[w]), e = __ldg(&g_off[w+1]);
    const float4* h4 = (const float4*)g_h;
    float4 acc = make_float4(0.f,0.f,0.f,0.f);
    int p = s;
    for (; p + 1 < e; p += 2){
        int s0 = __ldg(&g_csr[p]);
        int s1 = __ldg(&g_csr[p+1]);
        float4 v0 = __ldg(h4 + (size_t)s0*32 + lane);
        float4 v1 = __ldg(h4 + (size_t)s1*32 + lane);
        acc.x += v0.x; acc.y += v0.y; acc.z += v0.z; acc.w += v0.w;
        acc.x += v1.x; acc.y += v1.y; acc.z += v1.z; acc.w += v1.w;
    }
    if (p < e){
        int s0 = __ldg(&g_csr[p]);
        float4 v0 = __ldg(h4 + (size_t)s0*32 + lane);
        acc.x += v0.x; acc.y += v0.y; acc.z += v0.z; acc.w += v0.w;
    }
    ((float4*)g_m)[(size_t)w*32 + lane] = acc;
}

// ---------------- input layer (FFMA2) ----------------
__global__ __launch_bounds__(256) void k_input(const float* __restrict__ x,
                                               const float* __restrict__ bin){
    extern __shared__ float sm[];
    float4* Ws4 = (float4*)sm;
    float4* Xs4 = (float4*)(sm + IND*HH);
    int tid = threadIdx.x;
    int jt = tid & 31, nt = tid >> 5;

    const float4* Wg = (const float4*)g_Wint;
#pragma unroll
    for (int i = 0; i < 8; i++) Ws4[tid + i*256] = Wg[tid + i*256];

    int base = blockIdx.x * 64;
    const float4* Xg = (const float4*)x;
#pragma unroll
    for (int i = 0; i < 4; i++){
        int q = tid + i*256;
        int rn = q >> 4, col = q & 15;
        int gn = base + rn;
        Xs4[q] = (gn < NN) ? Xg[gn*16 + col] : make_float4(0.f,0.f,0.f,0.f);
    }
    __syncthreads();

    u64 acc[8][2];
#pragma unroll
    for (int i = 0; i < 8; i++){ acc[i][0] = 0ull; acc[i][1] = 0ull; }

    for (int k = 0; k < IND; k += 4){
        float a[8][4];
#pragma unroll
        for (int i = 0; i < 8; i++){
            float4 t4 = Xs4[(nt*8+i)*16 + (k>>2)];
            a[i][0]=t4.x; a[i][1]=t4.y; a[i][2]=t4.z; a[i][3]=t4.w;
        }
#pragma unroll
        for (int kk = 0; kk < 4; kk++){
            ulonglong2 wv = ((const ulonglong2*)Ws4)[(k+kk)*32 + jt];
#pragma unroll
            for (int i = 0; i < 8; i++){
                u64 a2 = dup2(a[i][kk]);
                ffma2(acc[i][0], a2, wv.x);
                ffma2(acc[i][1], a2, wv.y);
            }
        }
    }
    float4 bb = ((const float4*)bin)[jt];
#pragma unroll
    for (int i = 0; i < 8; i++){
        int n = base + nt*8 + i;
        if (n < NN){
            float2 z01 = unpk(acc[i][0]);
            float2 z23 = unpk(acc[i][1]);
            float4 o;
            o.x = fmaxf(z01.x+bb.x, 0.f);
            o.y = fmaxf(z01.y+bb.y, 0.f);
            o.z = fmaxf(z23.x+bb.z, 0.f);
            o.w = fmaxf(z23.y+bb.w, 0.f);
            ((float4*)g_h)[n*32 + jt] = o;
        }
    }
}

// ---------------- fused MGU step: one kernel does both dual-GEMMs per tile ----------------
// GEMM1: z1 = m@Wf^T + h@Uf^T + bf ; f = sigmoid(z1) (regs) ; g = f*h (SMEM)
// GEMM2: z2 = m@Wh^T + g@Uh^T + bh ; h_new = (1-f)*h + f*tanh(z2) -> global
// SMEM: weights (phase-swapped, 128KB) + m/h/g tiles (96KB) = 229376 B
#define SMF ((2*HH*HH + 3*64*HH) * 4)

__device__ __forceinline__ void loadWU(float4* Ws4, float4* Us4,
    const float4* Wg, const float4* Ug, int tid)
{
#pragma unroll
    for (int i = 0; i < 16; i++){
        Ws4[tid + i*256] = __ldg(Wg + tid + i*256);
        Us4[tid + i*256] = __ldg(Ug + tid + i*256);
    }
}

__device__ __forceinline__ void mgu_gemm(const float4* __restrict__ As4,
    const float4* __restrict__ Bs4, const float4* __restrict__ Ws4,
    const float4* __restrict__ Us4, int nt, int jt, u64 acc[8][2])
{
#pragma unroll
    for (int i = 0; i < 8; i++){ acc[i][0] = 0ull; acc[i][1] = 0ull; }
    for (int k = 0; k < HH; k += 4){
        float a[8][4], b[8][4];
#pragma unroll
        for (int i = 0; i < 8; i++){
            float4 ta = As4[(nt*8+i)*32 + (k>>2)];
            float4 tb = Bs4[(nt*8+i)*32 + (k>>2)];
            a[i][0]=ta.x; a[i][1]=ta.y; a[i][2]=ta.z; a[i][3]=ta.w;
            b[i][0]=tb.x; b[i][1]=tb.y; b[i][2]=tb.z; b[i][3]=tb.w;
        }
#pragma unroll
        for (int kk = 0; kk < 4; kk++){
            ulonglong2 wv = ((const ulonglong2*)Ws4)[(k+kk)*32 + jt];
            ulonglong2 uv = ((const ulonglong2*)Us4)[(k+kk)*32 + jt];
#pragma unroll
            for (int i = 0; i < 8; i++){
                u64 a2 = dup2(a[i][kk]);
                u64 b2 = dup2(b[i][kk]);
                ffma2(acc[i][0], a2, wv.x);
                ffma2(acc[i][1], a2, wv.y);
                ffma2(acc[i][0], b2, uv.x);
                ffma2(acc[i][1], b2, uv.y);
            }
        }
    }
}

__global__ __launch_bounds__(256, 1) void k_mgu(
    const float* __restrict__ A, float* __restrict__ H,
    const float* __restrict__ bfp, const float* __restrict__ bhp)
{
    extern __shared__ float sm[];
    float4* Ws4 = (float4*)sm;                          // 4096 f4 (phase weights W)
    float4* Us4 = (float4*)(sm + HH*HH);                // 4096 f4 (phase weights U)
    float4* As4 = (float4*)(sm + 2*HH*HH);              // m tile, 2048 f4
    float4* Hs4 = (float4*)(sm + 2*HH*HH + 64*HH);      // h tile
    float4* Gs4 = (float4*)(sm + 2*HH*HH + 2*64*HH);    // g tile
    int tid = threadIdx.x;
    int jt = tid & 31, nt = tid >> 5;

    float4 bf4 = ((const float4*)bfp)[jt];
    float4 bh4 = ((const float4*)bhp)[jt];
    const float4* Ag = (const float4*)A;
    const float4* Hg = (const float4*)H;
    const float4* Wfg = (const float4*)g_Wft;
    const float4* Ufg = (const float4*)g_Uft;
    const float4* Whg = (const float4*)g_Wht;
    const float4* Uhg = (const float4*)g_Uht;

    int ntiles = (NN + 63) >> 6;

    float4 pa[8], pb[8];
    {
        int base = blockIdx.x << 6;
#pragma unroll
        for (int i = 0; i < 8; i++){
            int gn = base + nt + i*8;   // matches store index tid + i*256
            if (gn < NN){ pa[i] = __ldg(Ag + (size_t)gn*32 + jt); pb[i] = __ldg(Hg + (size_t)gn*32 + jt); }
            else        { float4 z = make_float4(0.f,0.f,0.f,0.f); pa[i] = z; pb[i] = z; }
        }
    }

    for (int tile = blockIdx.x; tile < ntiles; tile += gridDim.x){
        int base = tile << 6;
        __syncthreads();   // prior tile's Hs4/As4 reads complete
#pragma unroll
        for (int i = 0; i < 8; i++){
            As4[tid + i*256] = pa[i];
            Hs4[tid + i*256] = pb[i];
        }
        loadWU(Ws4, Us4, Wfg, Ufg, tid);
        __syncthreads();

        // prefetch next tile while GEMM1 runs
        int ntile = tile + gridDim.x;
        if (ntile < ntiles){
            int nb = ntile << 6;
#pragma unroll
            for (int i = 0; i < 8; i++){
                int gn = nb + nt + i*8;
                if (gn < NN){ pa[i] = __ldg(Ag + (size_t)gn*32 + jt); pb[i] = __ldg(Hg + (size_t)gn*32 + jt); }
                else        { float4 z = make_float4(0.f,0.f,0.f,0.f); pa[i] = z; pb[i] = z; }
            }
        }

        u64 acc[8][2];
        mgu_gemm(As4, Hs4, Ws4, Us4, nt, jt, acc);

        // f = sigmoid(z1), g = f*h -> Gs4 ; keep f in regs
        float f[8][4];
#pragma unroll
        for (int i = 0; i < 8; i++){
            float2 z01 = unpk(acc[i][0]);
            float2 z23 = unpk(acc[i][1]);
            f[i][0] = sigf(z01.x + bf4.x);
            f[i][1] = sigf(z01.y + bf4.y);
            f[i][2] = sigf(z23.x + bf4.z);
            f[i][3] = sigf(z23.y + bf4.w);
            float4 hv = Hs4[(nt*8+i)*32 + jt];
            Gs4[(nt*8+i)*32 + jt] = make_float4(f[i][0]*hv.x, f[i][1]*hv.y, f[i][2]*hv.z, f[i][3]*hv.w);
        }
        __syncthreads();   // Gs4 complete; Ws4/Us4 free

        loadWU(Ws4, Us4, Whg, Uhg, tid);
        __syncthreads();

        mgu_gemm(As4, Gs4, Ws4, Us4, nt, jt, acc);

        // h_new = (1-f)*h + f*tanh(z2)
#pragma unroll
        for (int i = 0; i < 8; i++){
            int n = base + nt*8 + i;
            if (n < NN){
                float2 z01 = unpk(acc[i][0]);
                float2 z23 = unpk(acc[i][1]);
                float t0 = tanhfast(z01.x + bh4.x);
                float t1 = tanhfast(z01.y + bh4.y);
                float t2 = tanhfast(z23.x + bh4.z);
                float t3 = tanhfast(z23.y + bh4.w);
                float4 hv = Hs4[(nt*8+i)*32 + jt];
                float4 o;
                o.x = (1.f-f[i][0])*hv.x + f[i][0]*t0;
                o.y = (1.f-f[i][1])*hv.y + f[i][1]*t1;
                o.z = (1.f-f[i][2])*hv.z + f[i][2]*t2;
                o.w = (1.f-f[i][3])*hv.w + f[i][3]*t3;
                ((float4*)H)[(size_t)n*32 + jt] = o;
            }
        }
    }
}

// ---------------- fused Set2Set (3 steps LSTM+attn) + prediction ----------------
__global__ __launch_bounds__(256) void k_s2s(
    const float* __restrict__ wih, const float* __restrict__ whh,
    const float* __restrict__ bih, const float* __restrict__ bhh,
    const float* __restrict__ wp,  const float* __restrict__ bp,
    float* __restrict__ out)
{
    __shared__ __align__(16) float qs[2*HH];
    __shared__ __align__(16) float hl[HH];
    __shared__ __align__(16) float cl[HH];
    __shared__ float gt[4*HH];
    __shared__ float red[8];
    __shared__ __align__(16) float rp[8][HH];

    int g = blockIdx.x, t = threadIdx.x, wid = t >> 5, lane = t & 31;
    int s = g_bounds[g], e = g_bounds[g+1];
    const float4* h4 = (const float4*)g_h;

    if (t < HH){ hl[t] = 0.f; cl[t] = 0.f; }
    qs[t] = 0.f;
    __syncthreads();

    for (int step = 0; step < 3; step++){
        {
            const float4* qs4 = (const float4*)qs;
            const float4* hl4 = (const float4*)hl;
            float4 q0 = qs4[lane], q1 = qs4[32 + lane];
            float4 hh0 = hl4[lane];
            for (int r = wid*64; r < wid*64 + 64; r++){
                const float4* wr = (const float4*)(wih + (size_t)r*2*HH);
                const float4* hr = (const float4*)(whh + (size_t)r*HH);
                float4 w0 = __ldg(wr + lane);
                float4 w1 = __ldg(wr + 32 + lane);
                float4 h0 = __ldg(hr + lane);
                float p = w0.x*q0.x + w0.y*q0.y + w0.z*q0.z + w0.w*q0.w
                        + w1.x*q1.x + w1.y*q1.y + w1.z*q1.z + w1.w*q1.w
                        + h0.x*hh0.x + h0.y*hh0.y + h0.z*hh0.z + h0.w*hh0.w;
#pragma unroll
                for (int o = 16; o; o >>= 1) p += __shfl_xor_sync(0xffffffffu, p, o);
                if (lane == 0) gt[r] = p + __ldg(&bih[r]) + __ldg(&bhh[r]);
            }
        }
        __syncthreads();
        if (t < HH){
            float c = sigf(gt[HH+t])*cl[t] + sigf(gt[t])*tanhfast(gt[2*HH+t]);
            cl[t] = c;
            float hv = sigf(gt[3*HH+t])*tanhfast(c);
            hl[t] = hv;
            qs[t] = hv;
        }
        __syncthreads();

        float4 q4 = ((const float4*)hl)[lane];
        float lmax = -3.4e38f;
        for (int b = s + wid*4; b < e; b += 32){
            float p[4];
#pragma unroll
            for (int j = 0; j < 4; j++){
                if (b + j < e){
                    float4 x = __ldg(h4 + (size_t)(b+j)*32 + lane);
                    p[j] = x.x*q4.x + x.y*q4.y + x.z*q4.z + x.w*q4.w;
                } else p[j] = 0.f;
            }
#pragma unroll
            for (int o = 16; o; o >>= 1){
#pragma unroll
                for (int j = 0; j < 4; j++) p[j] += __shfl_xor_sync(0xffffffffu, p[j], o);
            }
#pragma unroll
            for (int j = 0; j < 4; j++){
                if (b + j < e){
                    if (lane == 0) g_e[b+j] = p[j];
                    lmax = fmaxf(lmax, p[j]);
                }
            }
        }
        if (lane == 0) red[wid] = lmax;
        __syncthreads();
        float emax = -3.4e38f;
#pragma unroll
        for (int w = 0; w < 8; w++) emax = fmaxf(emax, red[w]);
        __syncthreads();

        float lsum = 0.f;
        for (int n = s + t; n < e; n += 256){
            float w = __expf(g_e[n] - emax);
            g_e[n] = w;
            lsum += w;
        }
#pragma unroll
        for (int o = 16; o; o >>= 1) lsum += __shfl_xor_sync(0xffffffffu, lsum, o);
        if (lane == 0) red[wid] = lsum;
        __syncthreads();
        float denom = 0.f;
#pragma unroll
        for (int w = 0; w < 8; w++) denom += red[w];

        float4 racc = make_float4(0.f,0.f,0.f,0.f);
        for (int b = s + wid*4; b < e; b += 32){
#pragma unroll
            for (int j = 0; j < 4; j++){
                if (b + j < e){
                    float coef = __ldg(&g_e[b+j]);
                    float4 x = __ldg(h4 + (size_t)(b+j)*32 + lane);
                    racc.x += coef*x.x; racc.y += coef*x.y;
                    racc.z += coef*x.z; racc.w += coef*x.w;
                }
            }
        }
        ((float4*)rp[wid])[lane] = racc;
        __syncthreads();
        if (t < HH){
            float r = 0.f;
#pragma unroll
            for (int w = 0; w < 8; w++) r += rp[w][t];
            qs[HH + t] = (e > s) ? (r / denom) : 0.f;
        }
        __syncthreads();
    }

    float p = qs[t] * __ldg(&wp[t]);
#pragma unroll
    for (int o = 16; o; o >>= 1) p += __shfl_xor_sync(0xffffffffu, p, o);
    if (lane == 0) red[wid] = p;
    __syncthreads();
    if (t == 0){
        float r = 0.f;
#pragma unroll
        for (int w = 0; w < 8; w++) r += red[w];
        out[g] = r + __ldg(&bp[0]);
    }
}

// ---------------- launcher ----------------
extern "C" void kernel_launch(void* const* d_in, const int* in_sizes, int n_in,
                              void* d_out, int out_size){
    const float* x    = (const float*)d_in[0];
    const int*   ei   = (const int*)  d_in[1];
    const int*   batch= (const int*)  d_in[2];
    const float* Win  = (const float*)d_in[3];
    const float* bin  = (const float*)d_in[4];
    const float* Wf   = (const float*)d_in[5];
    const float* Uf   = (const float*)d_in[6];
    const float* bf   = (const float*)d_in[7];
    const float* Wh   = (const float*)d_in[8];
    const float* Uh   = (const float*)d_in[9];
    const float* bh   = (const float*)d_in[10];
    const float* wih  = (const float*)d_in[11];
    const float* whh  = (const float*)d_in[12];
    const float* bih  = (const float*)d_in[13];
    const float* bhh  = (const float*)d_in[14];
    const float* wp   = (const float*)d_in[15];
    const float* bp   = (const float*)d_in[16];
    float* out = (float*)d_out;

    float *p_m, *p_h;
    cudaGetSymbolAddress((void**)&p_m, g_m);
    cudaGetSymbolAddress((void**)&p_h, g_h);

    cudaFuncSetAttribute(k_mgu,   cudaFuncAttributeMaxDynamicSharedMemorySize, SMF);
    cudaFuncSetAttribute(k_input, cudaFuncAttributeMaxDynamicSharedMemorySize, 49152);

    const int* esrc = ei;
    const int* edst = ei + NE;
    const int NB1K = (NN + 1023) / 1024;

    k_prep5<<<dim3(4,4,5), dim3(32,32)>>>(Win, Wf, Uf, Wh, Uh);
    k_bounds<<<(NN+255)/256, 256>>>(batch);

    k_hist<<<(NE+255)/256, 256>>>(edst);
    k_scan1<<<NB1K, 1024>>>();
    k_scan2<<<1, 128>>>(NB1K);
    k_scan3<<<(NN+255)/256, 256>>>();
    k_fill<<<(NE+255)/256, 256>>>(esrc, edst);

    k_input<<<(NN+63)/64, 256, 49152>>>(x, bin);

    for (int step = 0; step < 3; step++){
        k_agg<<<(NN*32 + 255)/256, 256>>>();
        k_mgu<<<152, 256, SMF>>>(p_m, p_h, bf, bh);
    }

    k_s2s<<<NG, 256>>>(wih, whh, bih, bhh, wp, bp, out);
}

// round 11
// speedup vs baseline: 1.3401x; 1.0063x over previous
#include <cuda_runtime.h>
#include <cuda_bf16.h>
#include <math.h>
#include <stdint.h>

#define NN 100000
#define NE 640000
#define IND 64
#define HH  128
#define NG  128

typedef unsigned long long u64;

// ---------------- scratch (static device globals) ----------------
__device__ float g_h [NN*HH];
__device__ float g_m [NN*HH];
__device__ float g_Wint[IND*HH];
__device__ float g_Wft[HH*HH];
__device__ float g_Uft[HH*HH];
__device__ float g_Wht[HH*HH];
__device__ float g_Uht[HH*HH];
__device__ float g_e  [NN];
__device__ int   g_bounds[NG+1];
// CSR scratch
__device__ int g_deg[NN];
__device__ int g_off[NN+1];
__device__ int g_csr[NE];
__device__ int g_bsum[128];

__device__ __forceinline__ float sigf(float z)   { return __fdividef(1.f, 1.f + __expf(-z)); }
__device__ __forceinline__ float tanhfast(float z){ return 1.f - __fdividef(2.f, __expf(2.f*z) + 1.f); }

// ---- packed fp32x2 helpers (FFMA2) ----
__device__ __forceinline__ u64 dup2(float a){
    u64 r; asm("mov.b64 %0, {%1, %1};" : "=l"(r) : "f"(a)); return r;
}
__device__ __forceinline__ void ffma2(u64& d, u64 a, u64 b){
    asm("fma.rn.f32x2 %0, %1, %2, %0;" : "+l"(d) : "l"(a), "l"(b));
}
__device__ __forceinline__ float2 unpk(u64 v){
    float2 r; asm("mov.b64 {%0, %1}, %2;" : "=f"(r.x), "=f"(r.y) : "l"(v)); return r;
}

// ---------------- batched transpose of the 5 weight matrices ----------------
__global__ void k_prep5(const float* __restrict__ Win, const float* __restrict__ Wf,
                        const float* __restrict__ Uf,  const float* __restrict__ Wh,
                        const float* __restrict__ Uh){
    __shared__ float t[32][33];
    int mz = blockIdx.z;
    const float* src; float* dst; int R = 128, C = 128;
    switch (mz){
        case 0: src = Win; dst = g_Wint; C = 64; break;
        case 1: src = Wf;  dst = g_Wft; break;
        case 2: src = Uf;  dst = g_Uft; break;
        case 3: src = Wh;  dst = g_Wht; break;
        default: src = Uh; dst = g_Uht; break;
    }
    int c = blockIdx.x*32 + threadIdx.x;
    int r = blockIdx.y*32 + threadIdx.y;
    if (r < R && c < C) t[threadIdx.y][threadIdx.x] = src[r*C + c];
    __syncthreads();
    int rc = blockIdx.x*32 + threadIdx.y;
    int cc = blockIdx.y*32 + threadIdx.x;
    if (rc < C && cc < R) dst[rc*R + cc] = t[threadIdx.x][threadIdx.y];
}

// ---------------- bounds + zero deg ----------------
__global__ void k_bounds(const int* __restrict__ batch){
    int i = blockIdx.x*blockDim.x + threadIdx.x;
    if (i < NN) g_deg[i] = 0;
    if (i >= NN) return;
    int b = batch[i];
    if (i == 0)      { for (int g = 0;    g <= b;  g++) g_bounds[g] = 0; }
    else             { int pb = batch[i-1];
                       for (int g = pb+1; g <= b;  g++) g_bounds[g] = i; }
    if (i == NN-1)   { for (int g = b+1;  g <= NG; g++) g_bounds[g] = NN; }
}

// ---------------- CSR build ----------------
__global__ void k_hist(const int* __restrict__ dst){
    int e = blockIdx.x*blockDim.x + threadIdx.x;
    if (e < NE) atomicAdd(&g_deg[dst[e]], 1);
}
__global__ __launch_bounds__(1024) void k_scan1(){
    __shared__ int sd[1024];
    int t = threadIdx.x, i = blockIdx.x*1024 + t;
    int v = (i < NN) ? g_deg[i] : 0;
    sd[t] = v; __syncthreads();
#pragma unroll
    for (int o = 1; o < 1024; o <<= 1){
        int x = (t >= o) ? sd[t-o] : 0;
        __syncthreads();
        sd[t] += x;
        __syncthreads();
    }
    if (i < NN) g_off[i] = sd[t] - v;
    if (t == 1023) g_bsum[blockIdx.x] = sd[1023];
}
__global__ __launch_bounds__(128) void k_scan2(int nb){
    __shared__ int sd[128];
    int t = threadIdx.x;
    int v = (t < nb) ? g_bsum[t] : 0;
    sd[t] = v; __syncthreads();
#pragma unroll
    for (int o = 1; o < 128; o <<= 1){
        int x = (t >= o) ? sd[t-o] : 0;
        __syncthreads();
        sd[t] += x;
        __syncthreads();
    }
    if (t < nb) g_bsum[t] = sd[t] - v;
}
__global__ void k_scan3(){
    int i = blockIdx.x*blockDim.x + threadIdx.x;
    if (i < NN){ int o = g_off[i] + g_bsum[i >> 10]; g_off[i] = o; g_deg[i] = o; }
    if (i == 0) g_off[NN] = NE;
}
__global__ void k_fill(const int* __restrict__ src, const int* __restrict__ dst){
    int e = blockIdx.x*blockDim.x + threadIdx.x;
    if (e >= NE) return;
    int pos = atomicAdd(&g_deg[dst[e]], 1);
    g_csr[pos] = src[e];
}

// ---------------- aggregation: m[n] = sum_{e in csr[n]} h[src_e] ----------------
__global__ __launch_bounds__(256) void k_agg(){
    int w = (blockIdx.x*blockDim.x + threadIdx.x) >> 5;
    if (w >= NN) return;
    int lane = threadIdx.x & 31;
    int s = __ldg(&g_off[w]), e = __ldg(&g_off[w+1]);
    const float4* h4 = (const float4*)g_h;
    float4 acc = make_float4(0.f,0.f,0.f,0.f);
    int p = s;
    for (; p + 1 < e; p += 2){
        int s0 = __ldg(&g_csr[p]);
        int s1 = __ldg(&g_csr[p+1]);
        float4 v0 = __ldg(h4 + (size_t)s0*32 + lane);
        float4 v1 = __ldg(h4 + (size_t)s1*32 + lane);
        acc.x += v0.x; acc.y += v0.y; acc.z += v0.z; acc.w += v0.w;
        acc.x += v1.x; acc.y += v1.y; acc.z += v1.z; acc.w += v1.w;
    }
    if (p < e){
        int s0 = __ldg(&g_csr[p]);
        float4 v0 = __ldg(h4 + (size_t)s0*32 + lane);
        acc.x += v0.x; acc.y += v0.y; acc.z += v0.z; acc.w += v0.w;
    }
    ((float4*)g_m)[(size_t)w*32 + lane] = acc;
}

// ---------------- input layer (FFMA2) ----------------
__global__ __launch_bounds__(256) void k_input(const float* __restrict__ x,
                                               const float* __restrict__ bin){
    extern __shared__ float sm[];
    float4* Ws4 = (float4*)sm;
    float4* Xs4 = (float4*)(sm + IND*HH);
    int tid = threadIdx.x;
    int jt = tid & 31, nt = tid >> 5;

    const float4* Wg = (const float4*)g_Wint;
#pragma unroll
    for (int i = 0; i < 8; i++) Ws4[tid + i*256] = Wg[tid + i*256];

    int base = blockIdx.x * 64;
    const float4* Xg = (const float4*)x;
#pragma unroll
    for (int i = 0; i < 4; i++){
        int q = tid + i*256;
        int rn = q >> 4, col = q & 15;
        int gn = base + rn;
        Xs4[q] = (gn < NN) ? Xg[gn*16 + col] : make_float4(0.f,0.f,0.f,0.f);
    }
    __syncthreads();

    u64 acc[8][2];
#pragma unroll
    for (int i = 0; i < 8; i++){ acc[i][0] = 0ull; acc[i][1] = 0ull; }

    for (int k = 0; k < IND; k += 4){
        float a[8][4];
#pragma unroll
        for (int i = 0; i < 8; i++){
            float4 t4 = Xs4[(nt*8+i)*16 + (k>>2)];
            a[i][0]=t4.x; a[i][1]=t4.y; a[i][2]=t4.z; a[i][3]=t4.w;
        }
#pragma unroll
        for (int kk = 0; kk < 4; kk++){
            ulonglong2 wv = ((const ulonglong2*)Ws4)[(k+kk)*32 + jt];
#pragma unroll
            for (int i = 0; i < 8; i++){
                u64 a2 = dup2(a[i][kk]);
                ffma2(acc[i][0], a2, wv.x);
                ffma2(acc[i][1], a2, wv.y);
            }
        }
    }
    float4 bb = ((const float4*)bin)[jt];
#pragma unroll
    for (int i = 0; i < 8; i++){
        int n = base + nt*8 + i;
        if (n < NN){
            float2 z01 = unpk(acc[i][0]);
            float2 z23 = unpk(acc[i][1]);
            float4 o;
            o.x = fmaxf(z01.x+bb.x, 0.f);
            o.y = fmaxf(z01.y+bb.y, 0.f);
            o.z = fmaxf(z23.x+bb.z, 0.f);
            o.w = fmaxf(z23.y+bb.w, 0.f);
            ((float4*)g_h)[n*32 + jt] = o;
        }
    }
}

// ---------------- fused MGU step: one kernel does both dual-GEMMs per tile ----------------
// GEMM1: z1 = m@Wf^T + h@Uf^T + bf ; f = sigmoid(z1) (regs) ; g = f*h (SMEM)
// GEMM2: z2 = m@Wh^T + g@Uh^T + bh ; h_new = (1-f)*h + f*tanh(z2) -> global
// SMEM: weights (phase-swapped, 128KB) + m/h/g tiles (96KB) = 229376 B
#define SMF ((2*HH*HH + 3*64*HH) * 4)

__device__ __forceinline__ void loadWU(float4* Ws4, float4* Us4,
    const float4* Wg, const float4* Ug, int tid)
{
#pragma unroll
    for (int i = 0; i < 16; i++){
        Ws4[tid + i*256] = __ldg(Wg + tid + i*256);
        Us4[tid + i*256] = __ldg(Ug + tid + i*256);
    }
}

__device__ __forceinline__ void mgu_gemm(const float4* __restrict__ As4,
    const float4* __restrict__ Bs4, const float4* __restrict__ Ws4,
    const float4* __restrict__ Us4, int nt, int jt, u64 acc[8][2])
{
#pragma unroll
    for (int i = 0; i < 8; i++){ acc[i][0] = 0ull; acc[i][1] = 0ull; }
    for (int k = 0; k < HH; k += 4){
        float a[8][4], b[8][4];
#pragma unroll
        for (int i = 0; i < 8; i++){
            float4 ta = As4[(nt*8+i)*32 + (k>>2)];
            float4 tb = Bs4[(nt*8+i)*32 + (k>>2)];
            a[i][0]=ta.x; a[i][1]=ta.y; a[i][2]=ta.z; a[i][3]=ta.w;
            b[i][0]=tb.x; b[i][1]=tb.y; b[i][2]=tb.z; b[i][3]=tb.w;
        }
#pragma unroll
        for (int kk = 0; kk < 4; kk++){
            ulonglong2 wv = ((const ulonglong2*)Ws4)[(k+kk)*32 + jt];
            ulonglong2 uv = ((const ulonglong2*)Us4)[(k+kk)*32 + jt];
#pragma unroll
            for (int i = 0; i < 8; i++){
                u64 a2 = dup2(a[i][kk]);
                u64 b2 = dup2(b[i][kk]);
                ffma2(acc[i][0], a2, wv.x);
                ffma2(acc[i][1], a2, wv.y);
                ffma2(acc[i][0], b2, uv.x);
                ffma2(acc[i][1], b2, uv.y);
            }
        }
    }
}

__global__ __launch_bounds__(256, 1) void k_mgu(
    const float* __restrict__ A, float* __restrict__ H,
    const float* __restrict__ bfp, const float* __restrict__ bhp)
{
    extern __shared__ float sm[];
    float4* Ws4 = (float4*)sm;                          // 4096 f4 (phase weights W)
    float4* Us4 = (float4*)(sm + HH*HH);                // 4096 f4 (phase weights U)
    float4* As4 = (float4*)(sm + 2*HH*HH);              // m tile, 2048 f4
    float4* Hs4 = (float4*)(sm + 2*HH*HH + 64*HH);      // h tile
    float4* Gs4 = (float4*)(sm + 2*HH*HH + 2*64*HH);    // g tile
    int tid = threadIdx.x;
    int jt = tid & 31, nt = tid >> 5;

    float4 bf4 = ((const float4*)bfp)[jt];
    float4 bh4 = ((const float4*)bhp)[jt];
    const float4* Ag = (const float4*)A;
    const float4* Hg = (const float4*)H;
    const float4* Wfg = (const float4*)g_Wft;
    const float4* Ufg = (const float4*)g_Uft;
    const float4* Whg = (const float4*)g_Wht;
    const float4* Uhg = (const float4*)g_Uht;

    int ntiles = (NN + 63) >> 6;

    float4 pa[8], pb[8];
    {
        int base = blockIdx.x << 6;
#pragma unroll
        for (int i = 0; i < 8; i++){
            int gn = base + nt + i*8;   // matches store index tid + i*256
            if (gn < NN){ pa[i] = __ldg(Ag + (size_t)gn*32 + jt); pb[i] = __ldg(Hg + (size_t)gn*32 + jt); }
            else        { float4 z = make_float4(0.f,0.f,0.f,0.f); pa[i] = z; pb[i] = z; }
        }
    }

    for (int tile = blockIdx.x; tile < ntiles; tile += gridDim.x){
        int base = tile << 6;
        __syncthreads();   // prior tile's Hs4/As4 reads complete
#pragma unroll
        for (int i = 0; i < 8; i++){
            As4[tid + i*256] = pa[i];
            Hs4[tid + i*256] = pb[i];
        }
        loadWU(Ws4, Us4, Wfg, Ufg, tid);
        __syncthreads();

        // prefetch next tile while GEMM1 runs
        int ntile = tile + gridDim.x;
        if (ntile < ntiles){
            int nb = ntile << 6;
#pragma unroll
            for (int i = 0; i < 8; i++){
                int gn = nb + nt + i*8;
                if (gn < NN){ pa[i] = __ldg(Ag + (size_t)gn*32 + jt); pb[i] = __ldg(Hg + (size_t)gn*32 + jt); }
                else        { float4 z = make_float4(0.f,0.f,0.f,0.f); pa[i] = z; pb[i] = z; }
            }
        }

        u64 acc[8][2];
        mgu_gemm(As4, Hs4, Ws4, Us4, nt, jt, acc);

        // f = sigmoid(z1), g = f*h -> Gs4 ; keep f in regs
        float f[8][4];
#pragma unroll
        for (int i = 0; i < 8; i++){
            float2 z01 = unpk(acc[i][0]);
            float2 z23 = unpk(acc[i][1]);
            f[i][0] = sigf(z01.x + bf4.x);
            f[i][1] = sigf(z01.y + bf4.y);
            f[i][2] = sigf(z23.x + bf4.z);
            f[i][3] = sigf(z23.y + bf4.w);
            float4 hv = Hs4[(nt*8+i)*32 + jt];
            Gs4[(nt*8+i)*32 + jt] = make_float4(f[i][0]*hv.x, f[i][1]*hv.y, f[i][2]*hv.z, f[i][3]*hv.w);
        }
        __syncthreads();   // Gs4 complete; Ws4/Us4 free

        loadWU(Ws4, Us4, Whg, Uhg, tid);
        __syncthreads();

        mgu_gemm(As4, Gs4, Ws4, Us4, nt, jt, acc);

        // h_new = (1-f)*h + f*tanh(z2)
#pragma unroll
        for (int i = 0; i < 8; i++){
            int n = base + nt*8 + i;
            if (n < NN){
                float2 z01 = unpk(acc[i][0]);
                float2 z23 = unpk(acc[i][1]);
                float t0 = tanhfast(z01.x + bh4.x);
                float t1 = tanhfast(z01.y + bh4.y);
                float t2 = tanhfast(z23.x + bh4.z);
                float t3 = tanhfast(z23.y + bh4.w);
                float4 hv = Hs4[(nt*8+i)*32 + jt];
                float4 o;
                o.x = (1.f-f[i][0])*hv.x + f[i][0]*t0;
                o.y = (1.f-f[i][1])*hv.y + f[i][1]*t1;
                o.z = (1.f-f[i][2])*hv.z + f[i][2]*t2;
                o.w = (1.f-f[i][3])*hv.w + f[i][3]*t3;
                ((float4*)H)[(size_t)n*32 + jt] = o;
            }
        }
    }
}

// ---------------- fused Set2Set (3 steps LSTM+attn) + prediction ----------------
__global__ __launch_bounds__(256) void k_s2s(
    const float* __restrict__ wih, const float* __restrict__ whh,
    const float* __restrict__ bih, const float* __restrict__ bhh,
    const float* __restrict__ wp,  const float* __restrict__ bp,
    float* __restrict__ out)
{
    __shared__ __align__(16) float qs[2*HH];
    __shared__ __align__(16) float hl[HH];
    __shared__ __align__(16) float cl[HH];
    __shared__ float gt[4*HH];
    __shared__ float red[8];
    __shared__ __align__(16) float rp[8][HH];

    int g = blockIdx.x, t = threadIdx.x, wid = t >> 5, lane = t & 31;
    int s = g_bounds[g], e = g_bounds[g+1];
    const float4* h4 = (const float4*)g_h;

    if (t < HH){ hl[t] = 0.f; cl[t] = 0.f; }
    qs[t] = 0.f;
    __syncthreads();

    for (int step = 0; step < 3; step++){
        {
            const float4* qs4 = (const float4*)qs;
            const float4* hl4 = (const float4*)hl;
            float4 q0 = qs4[lane], q1 = qs4[32 + lane];
            float4 hh0 = hl4[lane];
            for (int r = wid*64; r < wid*64 + 64; r++){
                const float4* wr = (const float4*)(wih + (size_t)r*2*HH);
                const float4* hr = (const float4*)(whh + (size_t)r*HH);
                float4 w0 = __ldg(wr + lane);
                float4 w1 = __ldg(wr + 32 + lane);
                float4 h0 = __ldg(hr + lane);
                float p = w0.x*q0.x + w0.y*q0.y + w0.z*q0.z + w0.w*q0.w
                        + w1.x*q1.x + w1.y*q1.y + w1.z*q1.z + w1.w*q1.w
                        + h0.x*hh0.x + h0.y*hh0.y + h0.z*hh0.z + h0.w*hh0.w;
#pragma unroll
                for (int o = 16; o; o >>= 1) p += __shfl_xor_sync(0xffffffffu, p, o);
                if (lane == 0) gt[r] = p + __ldg(&bih[r]) + __ldg(&bhh[r]);
            }
        }
        __syncthreads();
        if (t < HH){
            float c = sigf(gt[HH+t])*cl[t] + sigf(gt[t])*tanhfast(gt[2*HH+t]);
            cl[t] = c;
            float hv = sigf(gt[3*HH+t])*tanhfast(c);
            hl[t] = hv;
            qs[t] = hv;
        }
        __syncthreads();

        float4 q4 = ((const float4*)hl)[lane];
        float lmax = -3.4e38f;
        for (int b = s + wid*4; b < e; b += 32){
            float p[4];
#pragma unroll
            for (int j = 0; j < 4; j++){
                if (b + j < e){
                    float4 x = __ldg(h4 + (size_t)(b+j)*32 + lane);
                    p[j] = x.x*q4.x + x.y*q4.y + x.z*q4.z + x.w*q4.w;
                } else p[j] = 0.f;
            }
#pragma unroll
            for (int o = 16; o; o >>= 1){
#pragma unroll
                for (int j = 0; j < 4; j++) p[j] += __shfl_xor_sync(0xffffffffu, p[j], o);
            }
#pragma unroll
            for (int j = 0; j < 4; j++){
                if (b + j < e){
                    if (lane == 0) g_e[b+j] = p[j];
                    lmax = fmaxf(lmax, p[j]);
                }
            }
        }
        if (lane == 0) red[wid] = lmax;
        __syncthreads();
        float emax = -3.4e38f;
#pragma unroll
        for (int w = 0; w < 8; w++) emax = fmaxf(emax, red[w]);
        __syncthreads();

        float lsum = 0.f;
        for (int n = s + t; n < e; n += 256){
            float w = __expf(g_e[n] - emax);
            g_e[n] = w;
            lsum += w;
        }
#pragma unroll
        for (int o = 16; o; o >>= 1) lsum += __shfl_xor_sync(0xffffffffu, lsum, o);
        if (lane == 0) red[wid] = lsum;
        __syncthreads();
        float denom = 0.f;
#pragma unroll
        for (int w = 0; w < 8; w++) denom += red[w];

        float4 racc = make_float4(0.f,0.f,0.f,0.f);
        for (int b = s + wid*4; b < e; b += 32){
#pragma unroll
            for (int j = 0; j < 4; j++){
                if (b + j < e){
                    float coef = __ldg(&g_e[b+j]);
                    float4 x = __ldg(h4 + (size_t)(b+j)*32 + lane);
                    racc.x += coef*x.x; racc.y += coef*x.y;
                    racc.z += coef*x.z; racc.w += coef*x.w;
                }
            }
        }
        ((float4*)rp[wid])[lane] = racc;
        __syncthreads();
        if (t < HH){
            float r = 0.f;
#pragma unroll
            for (int w = 0; w < 8; w++) r += rp[w][t];
            qs[HH + t] = (e > s) ? (r / denom) : 0.f;
        }
        __syncthreads();
    }

    float p = qs[t] * __ldg(&wp[t]);
#pragma unroll
    for (int o = 16; o; o >>= 1) p += __shfl_xor_sync(0xffffffffu, p, o);
    if (lane == 0) red[wid] = p;
    __syncthreads();
    if (t == 0){
        float r = 0.f;
#pragma unroll
        for (int w = 0; w < 8; w++) r += red[w];
        out[g] = r + __ldg(&bp[0]);
    }
}

// ---------------- launcher ----------------
extern "C" void kernel_launch(void* const* d_in, const int* in_sizes, int n_in,
                              void* d_out, int out_size){
    const float* x    = (const float*)d_in[0];
    const int*   ei   = (const int*)  d_in[1];
    const int*   batch= (const int*)  d_in[2];
    const float* Win  = (const float*)d_in[3];
    const float* bin  = (const float*)d_in[4];
    const float* Wf   = (const float*)d_in[5];
    const float* Uf   = (const float*)d_in[6];
    const float* bf   = (const float*)d_in[7];
    const float* Wh   = (const float*)d_in[8];
    const float* Uh   = (const float*)d_in[9];
    const float* bh   = (const float*)d_in[10];
    const float* wih  = (const float*)d_in[11];
    const float* whh  = (const float*)d_in[12];
    const float* bih  = (const float*)d_in[13];
    const float* bhh  = (const float*)d_in[14];
    const float* wp   = (const float*)d_in[15];
    const float* bp   = (const float*)d_in[16];
    float* out = (float*)d_out;

    float *p_m, *p_h;
    cudaGetSymbolAddress((void**)&p_m, g_m);
    cudaGetSymbolAddress((void**)&p_h, g_h);

    cudaFuncSetAttribute(k_mgu,   cudaFuncAttributeMaxDynamicSharedMemorySize, SMF);
    cudaFuncSetAttribute(k_input, cudaFuncAttributeMaxDynamicSharedMemorySize, 49152);

    const int* esrc = ei;
    const int* edst = ei + NE;
    const int NB1K = (NN + 1023) / 1024;

    k_prep5<<<dim3(4,4,5), dim3(32,32)>>>(Win, Wf, Uf, Wh, Uh);
    k_bounds<<<(NN+255)/256, 256>>>(batch);

    k_hist<<<(NE+255)/256, 256>>>(edst);
    k_scan1<<<NB1K, 1024>>>();
    k_scan2<<<1, 128>>>(NB1K);
    k_scan3<<<(NN+255)/256, 256>>>();
    k_fill<<<(NE+255)/256, 256>>>(esrc, edst);

    k_input<<<(NN+63)/64, 256, 49152>>>(x, bin);

    for (int step = 0; step < 3; step++){
        k_agg<<<(NN*32 + 255)/256, 256>>>();
        k_mgu<<<152, 256, SMF>>>(p_m, p_h, bf, bh);
    }

    k_s2s<<<NG, 256>>>(wih, whh, bih, bhh, wp, bp, out);
}